// round 2
// baseline (speedup 1.0000x reference)
#include <cuda_runtime.h>
#include <cuda_bf16.h>

// Problem constants
#define BB  2
#define SS  2048
#define DD  1024
#define HH  16
#define DK  64
#define MROWS (BB*SS)   // 4096

// Scratch (allocation-free: __device__ globals)
__device__ float g_Q[BB*HH*SS*DK];   // [B,H,S,DK] 16 MB
__device__ float g_K[BB*HH*SS*DK];
__device__ float g_V[BB*HH*SS*DK];
__device__ float g_O[BB*SS*DD];      // [B,S,D] attention output

// ---------------------------------------------------------------------------
// Fused QKV projection: Y = X @ W^T + bias for 3 (X,W,bias) sets selected by
// blockIdx.z. BM=BN=128, BK=8, 256 threads, 8x8 micro-tile per thread.
// Epilogue writes split-head [B,H,S,DK] layout into g_Q/g_K/g_V.
// ---------------------------------------------------------------------------
__global__ __launch_bounds__(256)
void qkv_gemm_kernel(const float* __restrict__ q_in,
                     const float* __restrict__ k_in,
                     const float* __restrict__ v_in,
                     const float* __restrict__ Wq, const float* __restrict__ bq,
                     const float* __restrict__ Wk, const float* __restrict__ bk,
                     const float* __restrict__ Wv, const float* __restrict__ bv)
{
    const int BM = 128, BN = 128, BK = 8;
    __shared__ float As[BK][BM];
    __shared__ float Bs[BK][BN];

    int z = blockIdx.z;
    const float* X    = (z == 0) ? q_in : (z == 1) ? k_in : v_in;
    const float* W    = (z == 0) ? Wq   : (z == 1) ? Wk   : Wv;
    const float* bias = (z == 0) ? bq   : (z == 1) ? bk   : bv;
    float* Y          = (z == 0) ? g_Q  : (z == 1) ? g_K  : g_V;

    int tid  = threadIdx.x;
    int m0   = blockIdx.y * BM;
    int n0   = blockIdx.x * BN;
    int tRow = tid >> 4;       // 0..15
    int tCol = tid & 15;       // 0..15

    // loader: thread loads one float4 of A and one of B per BK-step
    int lr = tid >> 1;         // 0..127 (row within tile)
    int lc = (tid & 1) * 4;    // 0 or 4 (col within BK)
    const float* Xp = X + (size_t)(m0 + lr) * DD + lc;
    const float* Wp = W + (size_t)(n0 + lr) * DD + lc;

    float acc[8][8];
    #pragma unroll
    for (int i = 0; i < 8; i++)
        #pragma unroll
        for (int j = 0; j < 8; j++) acc[i][j] = 0.f;

    for (int k0 = 0; k0 < DD; k0 += BK) {
        float4 a = *(const float4*)(Xp + k0);
        float4 b = *(const float4*)(Wp + k0);
        As[lc+0][lr] = a.x; As[lc+1][lr] = a.y; As[lc+2][lr] = a.z; As[lc+3][lr] = a.w;
        Bs[lc+0][lr] = b.x; Bs[lc+1][lr] = b.y; Bs[lc+2][lr] = b.z; Bs[lc+3][lr] = b.w;
        __syncthreads();

        #pragma unroll
        for (int kk = 0; kk < BK; kk++) {
            float ra[8], rb[8];
            #pragma unroll
            for (int i = 0; i < 8; i++) ra[i] = As[kk][tRow*8 + i];
            #pragma unroll
            for (int j = 0; j < 8; j++) rb[j] = Bs[kk][tCol*8 + j];
            #pragma unroll
            for (int i = 0; i < 8; i++)
                #pragma unroll
                for (int j = 0; j < 8; j++)
                    acc[i][j] += ra[i] * rb[j];
        }
        __syncthreads();
    }

    // epilogue: split-head layout [B,H,S,DK]
    #pragma unroll
    for (int i = 0; i < 8; i++) {
        int m = m0 + tRow*8 + i;
        int b = m >> 11;              // /SS
        int s = m & (SS - 1);
        #pragma unroll
        for (int j = 0; j < 8; j++) {
            int n  = n0 + tCol*8 + j;
            int h  = n >> 6;
            int dk = n & 63;
            Y[(((size_t)(b*HH + h) * SS + s) * DK) + dk] = acc[i][j] + bias[n];
        }
    }
}

// ---------------------------------------------------------------------------
// Output projection: out = g_O @ Wo^T + bo, flat [M,D] output.
// ---------------------------------------------------------------------------
__global__ __launch_bounds__(256)
void out_gemm_kernel(const float* __restrict__ W, const float* __restrict__ bias,
                     float* __restrict__ Y)
{
    const int BM = 128, BN = 128, BK = 8;
    __shared__ float As[BK][BM];
    __shared__ float Bs[BK][BN];

    const float* X = g_O;

    int tid  = threadIdx.x;
    int m0   = blockIdx.y * BM;
    int n0   = blockIdx.x * BN;
    int tRow = tid >> 4;
    int tCol = tid & 15;

    int lr = tid >> 1;
    int lc = (tid & 1) * 4;
    const float* Xp = X + (size_t)(m0 + lr) * DD + lc;
    const float* Wp = W + (size_t)(n0 + lr) * DD + lc;

    float acc[8][8];
    #pragma unroll
    for (int i = 0; i < 8; i++)
        #pragma unroll
        for (int j = 0; j < 8; j++) acc[i][j] = 0.f;

    for (int k0 = 0; k0 < DD; k0 += BK) {
        float4 a = *(const float4*)(Xp + k0);
        float4 b = *(const float4*)(Wp + k0);
        As[lc+0][lr] = a.x; As[lc+1][lr] = a.y; As[lc+2][lr] = a.z; As[lc+3][lr] = a.w;
        Bs[lc+0][lr] = b.x; Bs[lc+1][lr] = b.y; Bs[lc+2][lr] = b.z; Bs[lc+3][lr] = b.w;
        __syncthreads();

        #pragma unroll
        for (int kk = 0; kk < BK; kk++) {
            float ra[8], rb[8];
            #pragma unroll
            for (int i = 0; i < 8; i++) ra[i] = As[kk][tRow*8 + i];
            #pragma unroll
            for (int j = 0; j < 8; j++) rb[j] = Bs[kk][tCol*8 + j];
            #pragma unroll
            for (int i = 0; i < 8; i++)
                #pragma unroll
                for (int j = 0; j < 8; j++)
                    acc[i][j] += ra[i] * rb[j];
        }
        __syncthreads();
    }

    #pragma unroll
    for (int i = 0; i < 8; i++) {
        int m = m0 + tRow*8 + i;
        #pragma unroll
        for (int j = 0; j < 8; j++) {
            int n = n0 + tCol*8 + j;
            Y[(size_t)m * DD + n] = acc[i][j] + bias[n];
        }
    }
}

// ---------------------------------------------------------------------------
// Flash attention (fp32): one CTA per (b, h, 64-query tile).
// 64x64 KV tiles, online softmax, 256 threads, 4x4 micro-tiles (16x16 grid).
// smem: Qt[64][64] (d-major), Kt[64][64] (d-major), Vs[64][64], Pt[64][68].
// ---------------------------------------------------------------------------
#define FA_SMEM ((3*64*64 + 64*68) * 4)   // 66560 bytes

__global__ __launch_bounds__(256)
void flash_kernel(const int* __restrict__ mask)
{
    extern __shared__ float sm[];
    float* Qt = sm;               // [d][r]  64*64
    float* Kt = Qt + 64*64;       // [d][c]  64*64
    float* Vs = Kt + 64*64;       // [c][dv] 64*64
    float* Pt = Vs + 64*64;       // [c][r]  64*68 (padded)

    int tid = threadIdx.x;
    int q0  = blockIdx.x * 64;
    int h   = blockIdx.y;
    int b   = blockIdx.z;
    size_t base = (size_t)(b*HH + h) * SS * DK;

    int tRow = tid >> 4, tCol = tid & 15;
    int r0 = tRow * 4, c0 = tCol * 4;

    // load Q transposed: thread handles row lr, 16 cols starting at (tid&3)*16
    int lr  = tid >> 2;
    int lcq = (tid & 3) * 16;
    {
        const float* Qg = g_Q + base + (size_t)(q0 + lr) * DK + lcq;
        #pragma unroll
        for (int u = 0; u < 4; u++) {
            float4 v4 = *(const float4*)(Qg + u*4);
            int c = lcq + u*4;
            Qt[(c+0)*64 + lr] = v4.x;
            Qt[(c+1)*64 + lr] = v4.y;
            Qt[(c+2)*64 + lr] = v4.z;
            Qt[(c+3)*64 + lr] = v4.w;
        }
    }

    float mrow[4], lrow[4], o[4][4];
    #pragma unroll
    for (int i = 0; i < 4; i++) {
        mrow[i] = -3.0e38f; lrow[i] = 0.f;
        #pragma unroll
        for (int j = 0; j < 4; j++) o[i][j] = 0.f;
    }

    for (int t = 0; t < SS/64; t++) {
        int kv0 = t * 64;
        __syncthreads();   // protect Kt/Vs/Pt from previous iteration readers

        // load K transposed + V direct
        {
            const float* Kg = g_K + base + (size_t)(kv0 + lr) * DK + lcq;
            #pragma unroll
            for (int u = 0; u < 4; u++) {
                float4 v4 = *(const float4*)(Kg + u*4);
                int c = lcq + u*4;
                Kt[(c+0)*64 + lr] = v4.x;
                Kt[(c+1)*64 + lr] = v4.y;
                Kt[(c+2)*64 + lr] = v4.z;
                Kt[(c+3)*64 + lr] = v4.w;
            }
            const float* Vg = g_V + base + (size_t)(kv0 + lr) * DK + lcq;
            #pragma unroll
            for (int u = 0; u < 4; u++) {
                *(float4*)&Vs[lr*64 + lcq + u*4] = *(const float4*)(Vg + u*4);
            }
        }
        __syncthreads();

        // scores S = (Q K^T) / 8, masked
        float sc[4][4];
        #pragma unroll
        for (int i = 0; i < 4; i++)
            #pragma unroll
            for (int j = 0; j < 4; j++) sc[i][j] = 0.f;

        #pragma unroll 8
        for (int d = 0; d < 64; d++) {
            float4 qv = *(const float4*)&Qt[d*64 + r0];
            float4 kv = *(const float4*)&Kt[d*64 + c0];
            float qa[4] = {qv.x, qv.y, qv.z, qv.w};
            float ka[4] = {kv.x, kv.y, kv.z, kv.w};
            #pragma unroll
            for (int i = 0; i < 4; i++)
                #pragma unroll
                for (int j = 0; j < 4; j++)
                    sc[i][j] += qa[i] * ka[j];
        }

        int mk[4];
        #pragma unroll
        for (int j = 0; j < 4; j++) mk[j] = mask[b*SS + kv0 + c0 + j];
        #pragma unroll
        for (int i = 0; i < 4; i++)
            #pragma unroll
            for (int j = 0; j < 4; j++) {
                float s = sc[i][j] * 0.125f;
                sc[i][j] = (mk[j] == 0) ? -1.0e9f : s;
            }

        // online softmax per row (16-lane groups share a row)
        #pragma unroll
        for (int i = 0; i < 4; i++) {
            float tm = fmaxf(fmaxf(sc[i][0], sc[i][1]), fmaxf(sc[i][2], sc[i][3]));
            #pragma unroll
            for (int off = 8; off >= 1; off >>= 1)
                tm = fmaxf(tm, __shfl_xor_sync(0xffffffffu, tm, off));
            float mn = fmaxf(mrow[i], tm);
            float al = __expf(mrow[i] - mn);
            float ts = 0.f;
            #pragma unroll
            for (int j = 0; j < 4; j++) {
                sc[i][j] = __expf(sc[i][j] - mn);   // now P
                ts += sc[i][j];
            }
            #pragma unroll
            for (int off = 8; off >= 1; off >>= 1)
                ts += __shfl_xor_sync(0xffffffffu, ts, off);
            lrow[i] = lrow[i] * al + ts;
            mrow[i] = mn;
            #pragma unroll
            for (int j = 0; j < 4; j++) o[i][j] *= al;
        }

        // write P transposed: Pt[c][r]
        #pragma unroll
        for (int j = 0; j < 4; j++) {
            float4 pv = make_float4(sc[0][j], sc[1][j], sc[2][j], sc[3][j]);
            *(float4*)&Pt[(c0 + j)*68 + r0] = pv;
        }
        __syncthreads();

        // O += P @ V
        #pragma unroll 8
        for (int c = 0; c < 64; c++) {
            float4 pv = *(const float4*)&Pt[c*68 + r0];
            float4 vv = *(const float4*)&Vs[c*64 + c0];
            float pa[4] = {pv.x, pv.y, pv.z, pv.w};
            float va[4] = {vv.x, vv.y, vv.z, vv.w};
            #pragma unroll
            for (int i = 0; i < 4; i++)
                #pragma unroll
                for (int j = 0; j < 4; j++)
                    o[i][j] += pa[i] * va[j];
        }
    }

    // normalize + write to g_O in [B,S,D] layout
    #pragma unroll
    for (int i = 0; i < 4; i++) {
        float inv = (lrow[i] > 0.f) ? (1.0f / lrow[i]) : 0.f;
        float4 ov = make_float4(o[i][0]*inv, o[i][1]*inv, o[i][2]*inv, o[i][3]*inv);
        size_t idx = ((size_t)b*SS + (q0 + r0 + i)) * DD + h*DK + c0;
        *(float4*)&g_O[idx] = ov;
    }
}

// ---------------------------------------------------------------------------
extern "C" void kernel_launch(void* const* d_in, const int* in_sizes, int n_in,
                              void* d_out, int out_size)
{
    const float* q    = (const float*)d_in[0];
    const float* k    = (const float*)d_in[1];
    const float* v    = (const float*)d_in[2];
    const int*   mask = (const int*)  d_in[3];
    const float* Wq   = (const float*)d_in[4];
    const float* bq   = (const float*)d_in[5];
    const float* Wk   = (const float*)d_in[6];
    const float* bk   = (const float*)d_in[7];
    const float* Wv   = (const float*)d_in[8];
    const float* bv   = (const float*)d_in[9];
    const float* Wo   = (const float*)d_in[10];
    const float* bo   = (const float*)d_in[11];
    float* out = (float*)d_out;

    // opt-in to >48KB dynamic smem (idempotent host-side call; capture-safe)
    cudaFuncSetAttribute(flash_kernel,
                         cudaFuncAttributeMaxDynamicSharedMemorySize, FA_SMEM);

    dim3 ggrid(DD/128, MROWS/128, 3);  // (8, 32, 3) — fused Q/K/V projections
    qkv_gemm_kernel<<<ggrid, 256>>>(q, k, v, Wq, bq, Wk, bk, Wv, bv);

    dim3 fgrid(SS/64, HH, BB);         // (32, 16, 2)
    flash_kernel<<<fgrid, 256, FA_SMEM>>>(mask);

    dim3 ogrid(DD/128, MROWS/128);     // (8, 32)
    out_gemm_kernel<<<ogrid, 256>>>(Wo, bo, out);
}

// round 4
// speedup vs baseline: 1.2690x; 1.2690x over previous
#include <cuda_runtime.h>
#include <cuda_bf16.h>
#include <cstdint>

// Problem constants
#define BB  2
#define SS  2048
#define DD  1024
#define HH  16
#define DK  64
#define MROWS (BB*SS)   // 4096
#define GK  1024

// ---------------------------------------------------------------------------
// Scratch (allocation-free: __device__ globals)
// ---------------------------------------------------------------------------
__device__ float g_Q[BB*HH*SS*DK];   // [B,H,S,DK] fp32 (flash inputs)
__device__ float g_K[BB*HH*SS*DK];
__device__ float g_V[BB*HH*SS*DK];

// bf16 hi/lo split buffers
__device__ __align__(256) __nv_bfloat16 g_qh[MROWS*DD], g_ql[MROWS*DD];
__device__ __align__(256) __nv_bfloat16 g_kh[MROWS*DD], g_kl[MROWS*DD];
__device__ __align__(256) __nv_bfloat16 g_vh[MROWS*DD], g_vl[MROWS*DD];
__device__ __align__(256) __nv_bfloat16 g_Oh[MROWS*DD], g_Ol[MROWS*DD];
__device__ __align__(256) __nv_bfloat16 g_Wqh[DD*DD], g_Wql[DD*DD];
__device__ __align__(256) __nv_bfloat16 g_Wkh[DD*DD], g_Wkl[DD*DD];
__device__ __align__(256) __nv_bfloat16 g_Wvh[DD*DD], g_Wvl[DD*DD];
__device__ __align__(256) __nv_bfloat16 g_Woh[DD*DD], g_Wol[DD*DD];

// ---------------------------------------------------------------------------
// Baseline PTX helpers (sm_80-era: safe on sm_100 non-'a' target)
// ---------------------------------------------------------------------------
__device__ __forceinline__ uint32_t smem_to_u32(const void* p) {
    uint32_t a;
    asm("{ .reg .u64 t; cvta.to.shared.u64 t, %1; cvt.u32.u64 %0, t; }" : "=r"(a) : "l"(p));
    return a;
}
#define CP_ASYNC16(sa, ga) \
    asm volatile("cp.async.cg.shared.global [%0], [%1], 16;" :: "r"(sa), "l"(ga))
#define CP_COMMIT() asm volatile("cp.async.commit_group;" ::: "memory")
#define CP_WAIT(N)  asm volatile("cp.async.wait_group %0;" :: "n"(N) : "memory")

#define LDSM_X4(r0, r1, r2, r3, addr) \
    asm volatile("ldmatrix.sync.aligned.m8n8.x4.shared.b16 {%0,%1,%2,%3}, [%4];" \
        : "=r"(r0), "=r"(r1), "=r"(r2), "=r"(r3) : "r"(addr))

#define MMA16816(c0, c1, c2, c3, a0, a1, a2, a3, b0, b1) \
    asm volatile("mma.sync.aligned.m16n8k16.row.col.f32.bf16.bf16.f32 " \
        "{%0,%1,%2,%3}, {%4,%5,%6,%7}, {%8,%9}, {%0,%1,%2,%3};" \
        : "+f"(c0), "+f"(c1), "+f"(c2), "+f"(c3) \
        : "r"(a0), "r"(a1), "r"(a2), "r"(a3), "r"(b0), "r"(b1))

// ---------------------------------------------------------------------------
// fp32 -> bf16 hi/lo split conversion (vectorized)
// ---------------------------------------------------------------------------
__global__ __launch_bounds__(256)
void conv_split_kernel(const float* __restrict__ src, __nv_bfloat16* __restrict__ hi,
                       __nv_bfloat16* __restrict__ lo, int n4)
{
    int i = blockIdx.x * blockDim.x + threadIdx.x;
    if (i >= n4) return;
    float4 v = ((const float4*)src)[i];
    float f[4] = {v.x, v.y, v.z, v.w};
    ushort4 hs, ls;
    unsigned short* hp = &hs.x;
    unsigned short* lp = &ls.x;
    #pragma unroll
    for (int j = 0; j < 4; j++) {
        __nv_bfloat16 h = __float2bfloat16(f[j]);
        __nv_bfloat16 l = __float2bfloat16(f[j] - __bfloat162float(h));
        hp[j] = __bfloat16_as_ushort(h);
        lp[j] = __bfloat16_as_ushort(l);
    }
    ((ushort4*)hi)[i] = hs;
    ((ushort4*)lo)[i] = ls;
}

// ---------------------------------------------------------------------------
// Tensor-core GEMM via mma.sync (bf16, 3-term hi/lo split, effective K=3072).
// Y = X @ W^T + bias.  128x128 CTA tile, 8 warps (2x4), 64x32 warp tile.
// BK=32 per stage (double-buffered cp.async), padded smem rows (40 bf16).
// Phase p = stage/32: p0 Ah*Bh, p1 Ah*Bl, p2 Al*Bh.
// ---------------------------------------------------------------------------
#define BKS 32
#define BKP 40
#define NSTAGE 96   // 3 * (1024/32)

__global__ __launch_bounds__(256)
void mma_gemm_kernel(const float* __restrict__ bias0, const float* __restrict__ bias1,
                     const float* __restrict__ bias2, float* __restrict__ Yext, int is_out)
{
    __shared__ __nv_bfloat16 As[2][128*BKP];
    __shared__ __nv_bfloat16 Bs[2][128*BKP];

    int tid = threadIdx.x, wid = tid >> 5, lane = tid & 31;
    int warp_m = wid >> 2;          // 0..1
    int warp_n = wid & 3;           // 0..3
    int m0 = blockIdx.y * 128, n0 = blockIdx.x * 128;
    int z = blockIdx.z;

    const __nv_bfloat16 *Ah, *Al, *Bh, *Bl;
    const float* bias;
    if (is_out)      { Ah = g_Oh; Al = g_Ol; Bh = g_Woh; Bl = g_Wol; bias = bias0; }
    else if (z == 0) { Ah = g_qh; Al = g_ql; Bh = g_Wqh; Bl = g_Wql; bias = bias0; }
    else if (z == 1) { Ah = g_kh; Al = g_kl; Bh = g_Wkh; Bl = g_Wkl; bias = bias1; }
    else             { Ah = g_vh; Al = g_vl; Bh = g_Wvh; Bl = g_Wvl; bias = bias2; }

    uint32_t sA[2] = { smem_to_u32(As[0]), smem_to_u32(As[1]) };
    uint32_t sB[2] = { smem_to_u32(Bs[0]), smem_to_u32(Bs[1]) };

    // loader mapping: row = tid>>1 (0..127), chunks c = (tid&1)*2 + {0,1} (16B each)
    int lrow = tid >> 1;
    int lc0  = (tid & 1) * 2;

    float c[4][4][4];
    #pragma unroll
    for (int i = 0; i < 4; i++)
        #pragma unroll
        for (int j = 0; j < 4; j++)
            #pragma unroll
            for (int r = 0; r < 4; r++) c[i][j][r] = 0.f;

    // ---- stage loader ----
    auto load_stage = [&](int s, int b) {
        int p   = s >> 5;
        int kin = (s & 31) * BKS;
        const __nv_bfloat16* Ap = (p == 2) ? Al : Ah;
        const __nv_bfloat16* Bp = (p == 1) ? Bl : Bh;
        #pragma unroll
        for (int i = 0; i < 2; i++) {
            int cc = lc0 + i;
            uint32_t soff = (uint32_t)(lrow * BKP + cc * 8) * 2;
            const __nv_bfloat16* ga = Ap + (size_t)(m0 + lrow) * GK + kin + cc * 8;
            const __nv_bfloat16* gb = Bp + (size_t)(n0 + lrow) * GK + kin + cc * 8;
            CP_ASYNC16(sA[b] + soff, ga);
            CP_ASYNC16(sB[b] + soff, gb);
        }
    };

    load_stage(0, 0);
    CP_COMMIT();

    int buf = 0;
    for (int s = 0; s < NSTAGE; s++) {
        int nb = buf ^ 1;
        if (s + 1 < NSTAGE) {
            load_stage(s + 1, nb);
            CP_COMMIT();
            CP_WAIT(1);
        } else {
            CP_WAIT(0);
        }
        __syncthreads();

        // compute on buf
        #pragma unroll
        for (int ks = 0; ks < BKS; ks += 16) {
            uint32_t a[4][4], bfr[4][2];
            #pragma unroll
            for (int fm = 0; fm < 4; fm++) {
                int r   = warp_m * 64 + fm * 16 + (lane & 15);
                int col = ks + ((lane >> 4) << 3);
                uint32_t addr = sA[buf] + (uint32_t)(r * BKP + col) * 2;
                LDSM_X4(a[fm][0], a[fm][1], a[fm][2], a[fm][3], addr);
            }
            #pragma unroll
            for (int gp = 0; gp < 2; gp++) {
                int r   = warp_n * 32 + gp * 16 + ((lane >> 4) << 3) + (lane & 7);
                int col = ks + (((lane >> 3) & 1) << 3);
                uint32_t addr = sB[buf] + (uint32_t)(r * BKP + col) * 2;
                uint32_t r0, r1, r2, r3;
                LDSM_X4(r0, r1, r2, r3, addr);
                bfr[gp*2][0] = r0; bfr[gp*2][1] = r1;
                bfr[gp*2+1][0] = r2; bfr[gp*2+1][1] = r3;
            }
            #pragma unroll
            for (int fm = 0; fm < 4; fm++)
                #pragma unroll
                for (int fn = 0; fn < 4; fn++)
                    MMA16816(c[fm][fn][0], c[fm][fn][1], c[fm][fn][2], c[fm][fn][3],
                             a[fm][0], a[fm][1], a[fm][2], a[fm][3],
                             bfr[fn][0], bfr[fn][1]);
        }
        __syncthreads();
        buf = nb;
    }

    // ---- epilogue: C frag thread mapping m16n8: row=lane/4 (+8), col=2*(lane%4) ----
    int grp = lane >> 2, q4 = (lane & 3) * 2;
    #pragma unroll
    for (int fm = 0; fm < 4; fm++) {
        #pragma unroll
        for (int fn = 0; fn < 4; fn++) {
            int n = n0 + warp_n * 32 + fn * 8 + q4;
            float b0 = bias[n], b1 = bias[n + 1];
            #pragma unroll
            for (int half = 0; half < 2; half++) {
                int m = m0 + warp_m * 64 + fm * 16 + grp + half * 8;
                float v0 = c[fm][fn][half*2 + 0] + b0;
                float v1 = c[fm][fn][half*2 + 1] + b1;
                if (is_out) {
                    float2* dst = (float2*)&Yext[(size_t)m * DD + n];
                    *dst = make_float2(v0, v1);
                } else {
                    float* Y = (z == 0) ? g_Q : (z == 1) ? g_K : g_V;
                    int bidx = m >> 11, srow = m & (SS - 1);
                    int h = n >> 6, dk = n & 63;
                    float2* dst = (float2*)&Y[(((size_t)(bidx*HH + h) * SS + srow) * DK) + dk];
                    *dst = make_float2(v0, v1);
                }
            }
        }
    }
}

// ---------------------------------------------------------------------------
// Flash attention (fp32): one CTA per (b, h, 64-query tile).  Epilogue writes
// bf16 hi/lo split of O for the final projection.
// ---------------------------------------------------------------------------
#define FA_SMEM ((3*64*64 + 64*68) * 4)   // 66560 bytes

__global__ __launch_bounds__(256)
void flash_kernel(const int* __restrict__ mask)
{
    extern __shared__ float sm[];
    float* Qt = sm;               // [d][r]  64*64
    float* Kt = Qt + 64*64;       // [d][c]  64*64
    float* Vs = Kt + 64*64;       // [c][dv] 64*64
    float* Pt = Vs + 64*64;       // [c][r]  64*68 (padded)

    int tid = threadIdx.x;
    int q0  = blockIdx.x * 64;
    int h   = blockIdx.y;
    int b   = blockIdx.z;
    size_t base = (size_t)(b*HH + h) * SS * DK;

    int tRow = tid >> 4, tCol = tid & 15;
    int r0 = tRow * 4, c0 = tCol * 4;

    int lr  = tid >> 2;
    int lcq = (tid & 3) * 16;
    {
        const float* Qg = g_Q + base + (size_t)(q0 + lr) * DK + lcq;
        #pragma unroll
        for (int u = 0; u < 4; u++) {
            float4 v4 = *(const float4*)(Qg + u*4);
            int c = lcq + u*4;
            Qt[(c+0)*64 + lr] = v4.x;
            Qt[(c+1)*64 + lr] = v4.y;
            Qt[(c+2)*64 + lr] = v4.z;
            Qt[(c+3)*64 + lr] = v4.w;
        }
    }

    float mrow[4], lrow[4], o[4][4];
    #pragma unroll
    for (int i = 0; i < 4; i++) {
        mrow[i] = -3.0e38f; lrow[i] = 0.f;
        #pragma unroll
        for (int j = 0; j < 4; j++) o[i][j] = 0.f;
    }

    for (int t = 0; t < SS/64; t++) {
        int kv0 = t * 64;
        __syncthreads();

        {
            const float* Kg = g_K + base + (size_t)(kv0 + lr) * DK + lcq;
            #pragma unroll
            for (int u = 0; u < 4; u++) {
                float4 v4 = *(const float4*)(Kg + u*4);
                int c = lcq + u*4;
                Kt[(c+0)*64 + lr] = v4.x;
                Kt[(c+1)*64 + lr] = v4.y;
                Kt[(c+2)*64 + lr] = v4.z;
                Kt[(c+3)*64 + lr] = v4.w;
            }
            const float* Vg = g_V + base + (size_t)(kv0 + lr) * DK + lcq;
            #pragma unroll
            for (int u = 0; u < 4; u++) {
                *(float4*)&Vs[lr*64 + lcq + u*4] = *(const float4*)(Vg + u*4);
            }
        }
        __syncthreads();

        float sc[4][4];
        #pragma unroll
        for (int i = 0; i < 4; i++)
            #pragma unroll
            for (int j = 0; j < 4; j++) sc[i][j] = 0.f;

        #pragma unroll 8
        for (int d = 0; d < 64; d++) {
            float4 qv = *(const float4*)&Qt[d*64 + r0];
            float4 kv = *(const float4*)&Kt[d*64 + c0];
            float qa[4] = {qv.x, qv.y, qv.z, qv.w};
            float ka[4] = {kv.x, kv.y, kv.z, kv.w};
            #pragma unroll
            for (int i = 0; i < 4; i++)
                #pragma unroll
                for (int j = 0; j < 4; j++)
                    sc[i][j] += qa[i] * ka[j];
        }

        int mk[4];
        #pragma unroll
        for (int j = 0; j < 4; j++) mk[j] = mask[b*SS + kv0 + c0 + j];
        #pragma unroll
        for (int i = 0; i < 4; i++)
            #pragma unroll
            for (int j = 0; j < 4; j++) {
                float s = sc[i][j] * 0.125f;
                sc[i][j] = (mk[j] == 0) ? -1.0e9f : s;
            }

        #pragma unroll
        for (int i = 0; i < 4; i++) {
            float tm = fmaxf(fmaxf(sc[i][0], sc[i][1]), fmaxf(sc[i][2], sc[i][3]));
            #pragma unroll
            for (int off = 8; off >= 1; off >>= 1)
                tm = fmaxf(tm, __shfl_xor_sync(0xffffffffu, tm, off));
            float mn = fmaxf(mrow[i], tm);
            float al = __expf(mrow[i] - mn);
            float ts = 0.f;
            #pragma unroll
            for (int j = 0; j < 4; j++) {
                sc[i][j] = __expf(sc[i][j] - mn);
                ts += sc[i][j];
            }
            #pragma unroll
            for (int off = 8; off >= 1; off >>= 1)
                ts += __shfl_xor_sync(0xffffffffu, ts, off);
            lrow[i] = lrow[i] * al + ts;
            mrow[i] = mn;
            #pragma unroll
            for (int j = 0; j < 4; j++) o[i][j] *= al;
        }

        #pragma unroll
        for (int j = 0; j < 4; j++) {
            float4 pv = make_float4(sc[0][j], sc[1][j], sc[2][j], sc[3][j]);
            *(float4*)&Pt[(c0 + j)*68 + r0] = pv;
        }
        __syncthreads();

        #pragma unroll 8
        for (int c = 0; c < 64; c++) {
            float4 pv = *(const float4*)&Pt[c*68 + r0];
            float4 vv = *(const float4*)&Vs[c*64 + c0];
            float pa[4] = {pv.x, pv.y, pv.z, pv.w};
            float va[4] = {vv.x, vv.y, vv.z, vv.w};
            #pragma unroll
            for (int i = 0; i < 4; i++)
                #pragma unroll
                for (int j = 0; j < 4; j++)
                    o[i][j] += pa[i] * va[j];
        }
    }

    // normalize + write bf16 hi/lo split for the O projection, [B,S,D] layout
    #pragma unroll
    for (int i = 0; i < 4; i++) {
        float inv = (lrow[i] > 0.f) ? (1.0f / lrow[i]) : 0.f;
        size_t idx = ((size_t)b*SS + (q0 + r0 + i)) * DD + h*DK + c0;
        #pragma unroll
        for (int j = 0; j < 4; j++) {
            float v = o[i][j] * inv;
            __nv_bfloat16 hb = __float2bfloat16(v);
            g_Oh[idx + j] = hb;
            g_Ol[idx + j] = __float2bfloat16(v - __bfloat162float(hb));
        }
    }
}

// ---------------------------------------------------------------------------
extern "C" void kernel_launch(void* const* d_in, const int* in_sizes, int n_in,
                              void* d_out, int out_size)
{
    const float* q    = (const float*)d_in[0];
    const float* k    = (const float*)d_in[1];
    const float* v    = (const float*)d_in[2];
    const int*   mask = (const int*)  d_in[3];
    const float* Wq   = (const float*)d_in[4];
    const float* bq   = (const float*)d_in[5];
    const float* Wk   = (const float*)d_in[6];
    const float* bk   = (const float*)d_in[7];
    const float* Wv   = (const float*)d_in[8];
    const float* bv   = (const float*)d_in[9];
    const float* Wo   = (const float*)d_in[10];
    const float* bo   = (const float*)d_in[11];
    float* out = (float*)d_out;

    // opt-in to >48KB dynamic smem for flash (idempotent, capture-safe)
    cudaFuncSetAttribute(flash_kernel,
                         cudaFuncAttributeMaxDynamicSharedMemorySize, FA_SMEM);

    // resolve device-global symbol addresses (host-side queries; capture-safe)
    __nv_bfloat16 *qh,*ql,*kh,*kl,*vh,*vl,*wqh,*wql,*wkh,*wkl,*wvh,*wvl,*woh,*wol;
    cudaGetSymbolAddress((void**)&qh,  g_qh);  cudaGetSymbolAddress((void**)&ql,  g_ql);
    cudaGetSymbolAddress((void**)&kh,  g_kh);  cudaGetSymbolAddress((void**)&kl,  g_kl);
    cudaGetSymbolAddress((void**)&vh,  g_vh);  cudaGetSymbolAddress((void**)&vl,  g_vl);
    cudaGetSymbolAddress((void**)&wqh, g_Wqh); cudaGetSymbolAddress((void**)&wql, g_Wql);
    cudaGetSymbolAddress((void**)&wkh, g_Wkh); cudaGetSymbolAddress((void**)&wkl, g_Wkl);
    cudaGetSymbolAddress((void**)&wvh, g_Wvh); cudaGetSymbolAddress((void**)&wvl, g_Wvl);
    cudaGetSymbolAddress((void**)&woh, g_Woh); cudaGetSymbolAddress((void**)&wol, g_Wol);

    // 1) fp32 -> bf16 hi/lo conversions
    const int NIN4 = MROWS*DD/4;
    const int NW4  = DD*DD/4;
    conv_split_kernel<<<(NIN4+255)/256, 256>>>(q, qh, ql, NIN4);
    conv_split_kernel<<<(NIN4+255)/256, 256>>>(k, kh, kl, NIN4);
    conv_split_kernel<<<(NIN4+255)/256, 256>>>(v, vh, vl, NIN4);
    conv_split_kernel<<<(NW4+255)/256, 256>>>(Wq, wqh, wql, NW4);
    conv_split_kernel<<<(NW4+255)/256, 256>>>(Wk, wkh, wkl, NW4);
    conv_split_kernel<<<(NW4+255)/256, 256>>>(Wv, wvh, wvl, NW4);
    conv_split_kernel<<<(NW4+255)/256, 256>>>(Wo, woh, wol, NW4);

    // 2) fused QKV projections on tensor cores (mma.sync)
    dim3 ggrid(DD/128, MROWS/128, 3);   // (8, 32, 3)
    mma_gemm_kernel<<<ggrid, 256>>>(bq, bk, bv, nullptr, 0);

    // 3) flash attention (fp32), writes g_Oh/g_Ol split directly
    dim3 fgrid(SS/64, HH, BB);          // (32, 16, 2)
    flash_kernel<<<fgrid, 256, FA_SMEM>>>(mask);

    // 4) output projection on tensor cores
    dim3 ogrid(DD/128, MROWS/128, 1);
    mma_gemm_kernel<<<ogrid, 256>>>(bo, nullptr, nullptr, out, 1);
}

// round 5
// speedup vs baseline: 2.8236x; 2.2250x over previous
#include <cuda_runtime.h>
#include <cuda_bf16.h>
#include <cuda_fp16.h>
#include <cstdint>

// Problem constants
#define BB  2
#define SS  2048
#define DD  1024
#define HH  16
#define DK  64
#define MROWS (BB*SS)   // 4096
#define GK  1024

// ---------------------------------------------------------------------------
// Scratch (allocation-free: __device__ globals)
// ---------------------------------------------------------------------------
// fp16 split-head Q/K/V for tensor-core flash
__device__ __align__(256) __half g_Qf[BB*HH*SS*DK];
__device__ __align__(256) __half g_Kf[BB*HH*SS*DK];
__device__ __align__(256) __half g_Vf[BB*HH*SS*DK];

// bf16 hi/lo split buffers (projection GEMMs)
__device__ __align__(256) __nv_bfloat16 g_qh[MROWS*DD], g_ql[MROWS*DD];
__device__ __align__(256) __nv_bfloat16 g_kh[MROWS*DD], g_kl[MROWS*DD];
__device__ __align__(256) __nv_bfloat16 g_vh[MROWS*DD], g_vl[MROWS*DD];
__device__ __align__(256) __nv_bfloat16 g_Oh[MROWS*DD], g_Ol[MROWS*DD];
__device__ __align__(256) __nv_bfloat16 g_Wqh[DD*DD], g_Wql[DD*DD];
__device__ __align__(256) __nv_bfloat16 g_Wkh[DD*DD], g_Wkl[DD*DD];
__device__ __align__(256) __nv_bfloat16 g_Wvh[DD*DD], g_Wvl[DD*DD];
__device__ __align__(256) __nv_bfloat16 g_Woh[DD*DD], g_Wol[DD*DD];

// ---------------------------------------------------------------------------
// Baseline PTX helpers (sm_80-era: compile for sm_100 non-'a' target)
// ---------------------------------------------------------------------------
__device__ __forceinline__ uint32_t smem_to_u32(const void* p) {
    uint32_t a;
    asm("{ .reg .u64 t; cvta.to.shared.u64 t, %1; cvt.u32.u64 %0, t; }" : "=r"(a) : "l"(p));
    return a;
}
#define CP_ASYNC16(sa, ga) \
    asm volatile("cp.async.cg.shared.global [%0], [%1], 16;" :: "r"(sa), "l"(ga))
#define CP_COMMIT() asm volatile("cp.async.commit_group;" ::: "memory")
#define CP_WAIT(N)  asm volatile("cp.async.wait_group %0;" :: "n"(N) : "memory")

#define LDSM_X4(r0, r1, r2, r3, addr) \
    asm volatile("ldmatrix.sync.aligned.m8n8.x4.shared.b16 {%0,%1,%2,%3}, [%4];" \
        : "=r"(r0), "=r"(r1), "=r"(r2), "=r"(r3) : "r"(addr))
#define LDSM_X4_T(r0, r1, r2, r3, addr) \
    asm volatile("ldmatrix.sync.aligned.m8n8.x4.trans.shared.b16 {%0,%1,%2,%3}, [%4];" \
        : "=r"(r0), "=r"(r1), "=r"(r2), "=r"(r3) : "r"(addr))

#define MMA_BF16(c0, c1, c2, c3, a0, a1, a2, a3, b0, b1) \
    asm volatile("mma.sync.aligned.m16n8k16.row.col.f32.bf16.bf16.f32 " \
        "{%0,%1,%2,%3}, {%4,%5,%6,%7}, {%8,%9}, {%0,%1,%2,%3};" \
        : "+f"(c0), "+f"(c1), "+f"(c2), "+f"(c3) \
        : "r"(a0), "r"(a1), "r"(a2), "r"(a3), "r"(b0), "r"(b1))
#define MMA_F16(c0, c1, c2, c3, a0, a1, a2, a3, b0, b1) \
    asm volatile("mma.sync.aligned.m16n8k16.row.col.f32.f16.f16.f32 " \
        "{%0,%1,%2,%3}, {%4,%5,%6,%7}, {%8,%9}, {%0,%1,%2,%3};" \
        : "+f"(c0), "+f"(c1), "+f"(c2), "+f"(c3) \
        : "r"(a0), "r"(a1), "r"(a2), "r"(a3), "r"(b0), "r"(b1))

__device__ __forceinline__ uint32_t pack_half2(float lo, float hi) {
    __half2 h = __floats2half2_rn(lo, hi);   // .x = lo (low 16 bits)
    return *(uint32_t*)&h;
}

// ---------------------------------------------------------------------------
// fp32 -> bf16 hi/lo split conversion (vectorized)
// ---------------------------------------------------------------------------
__global__ __launch_bounds__(256)
void conv_split_kernel(const float* __restrict__ src, __nv_bfloat16* __restrict__ hi,
                       __nv_bfloat16* __restrict__ lo, int n4)
{
    int i = blockIdx.x * blockDim.x + threadIdx.x;
    if (i >= n4) return;
    float4 v = ((const float4*)src)[i];
    float f[4] = {v.x, v.y, v.z, v.w};
    ushort4 hs, ls;
    unsigned short* hp = &hs.x;
    unsigned short* lp = &ls.x;
    #pragma unroll
    for (int j = 0; j < 4; j++) {
        __nv_bfloat16 h = __float2bfloat16(f[j]);
        __nv_bfloat16 l = __float2bfloat16(f[j] - __bfloat162float(h));
        hp[j] = __bfloat16_as_ushort(h);
        lp[j] = __bfloat16_as_ushort(l);
    }
    ((ushort4*)hi)[i] = hs;
    ((ushort4*)lo)[i] = ls;
}

// ---------------------------------------------------------------------------
// Tensor-core GEMM via mma.sync (bf16, 3-term hi/lo split, effective K=3072).
// Y = X @ W^T + bias.  128x128 CTA tile, 8 warps (2x4), 64x32 warp tile.
// QKV epilogue writes fp16 split-head [B,H,S,DK]; out epilogue writes fp32.
// ---------------------------------------------------------------------------
#define BKS 32
#define BKP 40
#define NSTAGE 96   // 3 * (1024/32)

__global__ __launch_bounds__(256)
void mma_gemm_kernel(const float* __restrict__ bias0, const float* __restrict__ bias1,
                     const float* __restrict__ bias2, float* __restrict__ Yext, int is_out)
{
    __shared__ __nv_bfloat16 As[2][128*BKP];
    __shared__ __nv_bfloat16 Bs[2][128*BKP];

    int tid = threadIdx.x, wid = tid >> 5, lane = tid & 31;
    int warp_m = wid >> 2;          // 0..1
    int warp_n = wid & 3;           // 0..3
    int m0 = blockIdx.y * 128, n0 = blockIdx.x * 128;
    int z = blockIdx.z;

    const __nv_bfloat16 *Ah, *Al, *Bh, *Bl;
    const float* bias;
    if (is_out)      { Ah = g_Oh; Al = g_Ol; Bh = g_Woh; Bl = g_Wol; bias = bias0; }
    else if (z == 0) { Ah = g_qh; Al = g_ql; Bh = g_Wqh; Bl = g_Wql; bias = bias0; }
    else if (z == 1) { Ah = g_kh; Al = g_kl; Bh = g_Wkh; Bl = g_Wkl; bias = bias1; }
    else             { Ah = g_vh; Al = g_vl; Bh = g_Wvh; Bl = g_Wvl; bias = bias2; }

    uint32_t sA[2] = { smem_to_u32(As[0]), smem_to_u32(As[1]) };
    uint32_t sB[2] = { smem_to_u32(Bs[0]), smem_to_u32(Bs[1]) };

    int lrow = tid >> 1;
    int lc0  = (tid & 1) * 2;

    float c[4][4][4];
    #pragma unroll
    for (int i = 0; i < 4; i++)
        #pragma unroll
        for (int j = 0; j < 4; j++)
            #pragma unroll
            for (int r = 0; r < 4; r++) c[i][j][r] = 0.f;

    auto load_stage = [&](int s, int b) {
        int p   = s >> 5;
        int kin = (s & 31) * BKS;
        const __nv_bfloat16* Ap = (p == 2) ? Al : Ah;
        const __nv_bfloat16* Bp = (p == 1) ? Bl : Bh;
        #pragma unroll
        for (int i = 0; i < 2; i++) {
            int cc = lc0 + i;
            uint32_t soff = (uint32_t)(lrow * BKP + cc * 8) * 2;
            const __nv_bfloat16* ga = Ap + (size_t)(m0 + lrow) * GK + kin + cc * 8;
            const __nv_bfloat16* gb = Bp + (size_t)(n0 + lrow) * GK + kin + cc * 8;
            CP_ASYNC16(sA[b] + soff, ga);
            CP_ASYNC16(sB[b] + soff, gb);
        }
    };

    load_stage(0, 0);
    CP_COMMIT();

    int buf = 0;
    for (int s = 0; s < NSTAGE; s++) {
        int nb = buf ^ 1;
        if (s + 1 < NSTAGE) {
            load_stage(s + 1, nb);
            CP_COMMIT();
            CP_WAIT(1);
        } else {
            CP_WAIT(0);
        }
        __syncthreads();

        #pragma unroll
        for (int ks = 0; ks < BKS; ks += 16) {
            uint32_t a[4][4], bfr[4][2];
            #pragma unroll
            for (int fm = 0; fm < 4; fm++) {
                int r   = warp_m * 64 + fm * 16 + (lane & 15);
                int col = ks + ((lane >> 4) << 3);
                uint32_t addr = sA[buf] + (uint32_t)(r * BKP + col) * 2;
                LDSM_X4(a[fm][0], a[fm][1], a[fm][2], a[fm][3], addr);
            }
            #pragma unroll
            for (int gp = 0; gp < 2; gp++) {
                int r   = warp_n * 32 + gp * 16 + ((lane >> 4) << 3) + (lane & 7);
                int col = ks + (((lane >> 3) & 1) << 3);
                uint32_t addr = sB[buf] + (uint32_t)(r * BKP + col) * 2;
                uint32_t r0, r1, r2, r3;
                LDSM_X4(r0, r1, r2, r3, addr);
                bfr[gp*2][0] = r0; bfr[gp*2][1] = r1;
                bfr[gp*2+1][0] = r2; bfr[gp*2+1][1] = r3;
            }
            #pragma unroll
            for (int fm = 0; fm < 4; fm++)
                #pragma unroll
                for (int fn = 0; fn < 4; fn++)
                    MMA_BF16(c[fm][fn][0], c[fm][fn][1], c[fm][fn][2], c[fm][fn][3],
                             a[fm][0], a[fm][1], a[fm][2], a[fm][3],
                             bfr[fn][0], bfr[fn][1]);
        }
        __syncthreads();
        buf = nb;
    }

    // epilogue: C frag mapping m16n8: row = lane/4 (+8), col = 2*(lane%4)
    int grp = lane >> 2, q4 = (lane & 3) * 2;
    #pragma unroll
    for (int fm = 0; fm < 4; fm++) {
        #pragma unroll
        for (int fn = 0; fn < 4; fn++) {
            int n = n0 + warp_n * 32 + fn * 8 + q4;
            float b0 = bias[n], b1 = bias[n + 1];
            #pragma unroll
            for (int half = 0; half < 2; half++) {
                int m = m0 + warp_m * 64 + fm * 16 + grp + half * 8;
                float v0 = c[fm][fn][half*2 + 0] + b0;
                float v1 = c[fm][fn][half*2 + 1] + b1;
                if (is_out) {
                    float2* dst = (float2*)&Yext[(size_t)m * DD + n];
                    *dst = make_float2(v0, v1);
                } else {
                    __half* Yf = (z == 0) ? g_Qf : (z == 1) ? g_Kf : g_Vf;
                    int bidx = m >> 11, srow = m & (SS - 1);
                    int h = n >> 6, dk = n & 63;
                    __half2 hv = __floats2half2_rn(v0, v1);
                    *(__half2*)&Yf[(((size_t)(bidx*HH + h) * SS + srow) * DK) + dk] = hv;
                }
            }
        }
    }
}

// ---------------------------------------------------------------------------
// Tensor-core flash attention (fp16 mma.sync, fp32 accum + softmax).
// CTA = (b, h, 64-query tile), 128 threads / 4 warps; warp w owns rows
// 16w..16w+15.  KV tiles of 64 keys, double-buffered cp.async.
// ---------------------------------------------------------------------------
#define LQ 72   // padded fp16 row stride (144 B -> conflict-free ldmatrix)

__global__ __launch_bounds__(128)
void flash_tc_kernel(const int* __restrict__ mask)
{
    __shared__ __half Qs[64*LQ];
    __shared__ __half Ks[2][64*LQ];
    __shared__ __half Vs[2][64*LQ];
    __shared__ int    Ms[2][64];

    int tid = threadIdx.x, w = tid >> 5, t = tid & 31;
    int q0 = blockIdx.x * 64;
    int h  = blockIdx.y;
    int b  = blockIdx.z;
    size_t base = (size_t)(b*HH + h) * SS * DK;

    uint32_t sQ  = smem_to_u32(Qs);
    uint32_t sK[2] = { smem_to_u32(Ks[0]), smem_to_u32(Ks[1]) };
    uint32_t sV[2] = { smem_to_u32(Vs[0]), smem_to_u32(Vs[1]) };
    uint32_t sM[2] = { smem_to_u32(Ms[0]), smem_to_u32(Ms[1]) };

    // loader mapping: row = tid>>1 (0..63), half-row = tid&1 (4 x 16B chunks)
    int lrow = tid >> 1, lhalf = tid & 1;

    // --- Q to smem (direct), first KV stage via cp.async ---
    {
        const uint4* src = (const uint4*)(g_Qf + base + (size_t)(q0 + lrow) * DK + lhalf * 32);
        uint4* dst = (uint4*)&Qs[lrow * LQ + lhalf * 32];
        #pragma unroll
        for (int i = 0; i < 4; i++) dst[i] = src[i];
    }
    auto load_stage = [&](int ti, int bn) {
        const __half* gk = g_Kf + base + (size_t)(ti*64 + lrow) * DK + lhalf * 32;
        const __half* gv = g_Vf + base + (size_t)(ti*64 + lrow) * DK + lhalf * 32;
        uint32_t so = (uint32_t)(lrow * LQ + lhalf * 32) * 2;
        #pragma unroll
        for (int ccc = 0; ccc < 4; ccc++) {
            CP_ASYNC16(sK[bn] + so + ccc*16, gk + ccc*8);
            CP_ASYNC16(sV[bn] + so + ccc*16, gv + ccc*8);
        }
        if (tid < 16) CP_ASYNC16(sM[bn] + tid*16, mask + b*SS + ti*64 + tid*4);
    };
    load_stage(0, 0);
    CP_COMMIT();
    __syncthreads();   // Qs visible

    // --- Q fragments (whole CTA lifetime) ---
    uint32_t qa[4][4];
    #pragma unroll
    for (int kt = 0; kt < 4; kt++) {
        uint32_t addr = sQ + (uint32_t)((w*16 + (t & 15)) * LQ + kt*16 + ((t >> 4) << 3)) * 2;
        LDSM_X4(qa[kt][0], qa[kt][1], qa[kt][2], qa[kt][3], addr);
    }

    float o[8][4];
    #pragma unroll
    for (int n = 0; n < 8; n++)
        #pragma unroll
        for (int i = 0; i < 4; i++) o[n][i] = 0.f;
    float m0r = -3.0e38f, m1r = -3.0e38f, l0 = 0.f, l1 = 0.f;

    int buf = 0;
    for (int ti = 0; ti < SS/64; ti++) {
        int nb = buf ^ 1;
        if (ti + 1 < SS/64) {
            load_stage(ti + 1, nb);
            CP_COMMIT();
            CP_WAIT(1);
        } else {
            CP_WAIT(0);
        }
        __syncthreads();

        // ---- scores: S = Q K^T (fp16 mma, f32 accum) ----
        float c[8][4];
        #pragma unroll
        for (int n = 0; n < 8; n++)
            #pragma unroll
            for (int i = 0; i < 4; i++) c[n][i] = 0.f;

        #pragma unroll
        for (int kt = 0; kt < 4; kt++) {
            #pragma unroll
            for (int np = 0; np < 4; np++) {
                uint32_t r0, r1, r2, r3;
                uint32_t addr = sK[buf] + (uint32_t)((np*16 + ((t >> 4) << 3) + (t & 7)) * LQ
                                                      + kt*16 + (((t >> 3) & 1) << 3)) * 2;
                LDSM_X4(r0, r1, r2, r3, addr);
                MMA_F16(c[2*np][0], c[2*np][1], c[2*np][2], c[2*np][3],
                        qa[kt][0], qa[kt][1], qa[kt][2], qa[kt][3], r0, r1);
                MMA_F16(c[2*np+1][0], c[2*np+1][1], c[2*np+1][2], c[2*np+1][3],
                        qa[kt][0], qa[kt][1], qa[kt][2], qa[kt][3], r2, r3);
            }
        }

        // ---- mask + scale ----
        #pragma unroll
        for (int n = 0; n < 8; n++) {
            int cb = n*8 + (t & 3)*2;
            int mb0 = Ms[buf][cb], mb1 = Ms[buf][cb + 1];
            c[n][0] = mb0 ? c[n][0]*0.125f : -1.0e9f;
            c[n][2] = mb0 ? c[n][2]*0.125f : -1.0e9f;
            c[n][1] = mb1 ? c[n][1]*0.125f : -1.0e9f;
            c[n][3] = mb1 ? c[n][3]*0.125f : -1.0e9f;
        }

        // ---- online softmax (rows r0 = t/4, r1 = t/4+8) ----
        float tm0 = -3.0e38f, tm1 = -3.0e38f;
        #pragma unroll
        for (int n = 0; n < 8; n++) {
            tm0 = fmaxf(tm0, fmaxf(c[n][0], c[n][1]));
            tm1 = fmaxf(tm1, fmaxf(c[n][2], c[n][3]));
        }
        tm0 = fmaxf(tm0, __shfl_xor_sync(0xffffffffu, tm0, 1));
        tm0 = fmaxf(tm0, __shfl_xor_sync(0xffffffffu, tm0, 2));
        tm1 = fmaxf(tm1, __shfl_xor_sync(0xffffffffu, tm1, 1));
        tm1 = fmaxf(tm1, __shfl_xor_sync(0xffffffffu, tm1, 2));

        float mn0 = fmaxf(m0r, tm0), mn1 = fmaxf(m1r, tm1);
        float al0 = __expf(m0r - mn0), al1 = __expf(m1r - mn1);
        float ts0 = 0.f, ts1 = 0.f;
        #pragma unroll
        for (int n = 0; n < 8; n++) {
            c[n][0] = __expf(c[n][0] - mn0); ts0 += c[n][0];
            c[n][1] = __expf(c[n][1] - mn0); ts0 += c[n][1];
            c[n][2] = __expf(c[n][2] - mn1); ts1 += c[n][2];
            c[n][3] = __expf(c[n][3] - mn1); ts1 += c[n][3];
        }
        ts0 += __shfl_xor_sync(0xffffffffu, ts0, 1);
        ts0 += __shfl_xor_sync(0xffffffffu, ts0, 2);
        ts1 += __shfl_xor_sync(0xffffffffu, ts1, 1);
        ts1 += __shfl_xor_sync(0xffffffffu, ts1, 2);
        l0 = l0*al0 + ts0; l1 = l1*al1 + ts1;
        m0r = mn0; m1r = mn1;
        #pragma unroll
        for (int n = 0; n < 8; n++) {
            o[n][0] *= al0; o[n][1] *= al0;
            o[n][2] *= al1; o[n][3] *= al1;
        }

        // ---- pack P into A-fragments (C(m16n8).c01/c23 -> a0..a3) ----
        uint32_t pa[4][4];
        #pragma unroll
        for (int kt = 0; kt < 4; kt++) {
            pa[kt][0] = pack_half2(c[2*kt][0],   c[2*kt][1]);
            pa[kt][1] = pack_half2(c[2*kt][2],   c[2*kt][3]);
            pa[kt][2] = pack_half2(c[2*kt+1][0], c[2*kt+1][1]);
            pa[kt][3] = pack_half2(c[2*kt+1][2], c[2*kt+1][3]);
        }

        // ---- O += P V  (V row-major, loaded as col-major B via ldmatrix.trans) ----
        #pragma unroll
        for (int kt = 0; kt < 4; kt++) {
            #pragma unroll
            for (int nh = 0; nh < 4; nh++) {
                uint32_t r0, r1, r2, r3;
                uint32_t addr = sV[buf] + (uint32_t)((kt*16 + (t & 15)) * LQ
                                                      + nh*16 + ((t >> 4) << 3)) * 2;
                LDSM_X4_T(r0, r1, r2, r3, addr);
                MMA_F16(o[2*nh][0], o[2*nh][1], o[2*nh][2], o[2*nh][3],
                        pa[kt][0], pa[kt][1], pa[kt][2], pa[kt][3], r0, r1);
                MMA_F16(o[2*nh+1][0], o[2*nh+1][1], o[2*nh+1][2], o[2*nh+1][3],
                        pa[kt][0], pa[kt][1], pa[kt][2], pa[kt][3], r2, r3);
            }
        }

        __syncthreads();
        buf = nb;
    }

    // ---- normalize + write bf16 hi/lo split of O, [B,S,D] layout ----
    float inv0 = (l0 > 0.f) ? (1.0f / l0) : 0.f;
    float inv1 = (l1 > 0.f) ? (1.0f / l1) : 0.f;
    int qr0 = q0 + w*16 + (t >> 2), qr1 = qr0 + 8;
    int dbase = (t & 3) * 2;
    #pragma unroll
    for (int n = 0; n < 8; n++) {
        int d = n*8 + dbase;
        size_t i0 = ((size_t)b*SS + qr0) * DD + h*DK + d;
        size_t i1 = ((size_t)b*SS + qr1) * DD + h*DK + d;
        float v0 = o[n][0]*inv0, v1 = o[n][1]*inv0;
        float v2 = o[n][2]*inv1, v3 = o[n][3]*inv1;
        __nv_bfloat16 h0 = __float2bfloat16(v0), h1 = __float2bfloat16(v1);
        __nv_bfloat16 h2 = __float2bfloat16(v2), h3 = __float2bfloat16(v3);
        *(__nv_bfloat162*)&g_Oh[i0] = __nv_bfloat162(h0, h1);
        *(__nv_bfloat162*)&g_Ol[i0] = __nv_bfloat162(
            __float2bfloat16(v0 - __bfloat162float(h0)),
            __float2bfloat16(v1 - __bfloat162float(h1)));
        *(__nv_bfloat162*)&g_Oh[i1] = __nv_bfloat162(h2, h3);
        *(__nv_bfloat162*)&g_Ol[i1] = __nv_bfloat162(
            __float2bfloat16(v2 - __bfloat162float(h2)),
            __float2bfloat16(v3 - __bfloat162float(h3)));
    }
}

// ---------------------------------------------------------------------------
extern "C" void kernel_launch(void* const* d_in, const int* in_sizes, int n_in,
                              void* d_out, int out_size)
{
    const float* q    = (const float*)d_in[0];
    const float* k    = (const float*)d_in[1];
    const float* v    = (const float*)d_in[2];
    const int*   mask = (const int*)  d_in[3];
    const float* Wq   = (const float*)d_in[4];
    const float* bq   = (const float*)d_in[5];
    const float* Wk   = (const float*)d_in[6];
    const float* bk   = (const float*)d_in[7];
    const float* Wv   = (const float*)d_in[8];
    const float* bv   = (const float*)d_in[9];
    const float* Wo   = (const float*)d_in[10];
    const float* bo   = (const float*)d_in[11];
    float* out = (float*)d_out;

    // resolve device-global symbol addresses (host-side queries; capture-safe)
    __nv_bfloat16 *qh,*ql,*kh,*kl,*vh,*vl,*wqh,*wql,*wkh,*wkl,*wvh,*wvl,*woh,*wol;
    cudaGetSymbolAddress((void**)&qh,  g_qh);  cudaGetSymbolAddress((void**)&ql,  g_ql);
    cudaGetSymbolAddress((void**)&kh,  g_kh);  cudaGetSymbolAddress((void**)&kl,  g_kl);
    cudaGetSymbolAddress((void**)&vh,  g_vh);  cudaGetSymbolAddress((void**)&vl,  g_vl);
    cudaGetSymbolAddress((void**)&wqh, g_Wqh); cudaGetSymbolAddress((void**)&wql, g_Wql);
    cudaGetSymbolAddress((void**)&wkh, g_Wkh); cudaGetSymbolAddress((void**)&wkl, g_Wkl);
    cudaGetSymbolAddress((void**)&wvh, g_Wvh); cudaGetSymbolAddress((void**)&wvl, g_Wvl);
    cudaGetSymbolAddress((void**)&woh, g_Woh); cudaGetSymbolAddress((void**)&wol, g_Wol);

    // 1) fp32 -> bf16 hi/lo conversions
    const int NIN4 = MROWS*DD/4;
    const int NW4  = DD*DD/4;
    conv_split_kernel<<<(NIN4+255)/256, 256>>>(q, qh, ql, NIN4);
    conv_split_kernel<<<(NIN4+255)/256, 256>>>(k, kh, kl, NIN4);
    conv_split_kernel<<<(NIN4+255)/256, 256>>>(v, vh, vl, NIN4);
    conv_split_kernel<<<(NW4+255)/256, 256>>>(Wq, wqh, wql, NW4);
    conv_split_kernel<<<(NW4+255)/256, 256>>>(Wk, wkh, wkl, NW4);
    conv_split_kernel<<<(NW4+255)/256, 256>>>(Wv, wvh, wvl, NW4);
    conv_split_kernel<<<(NW4+255)/256, 256>>>(Wo, woh, wol, NW4);

    // 2) fused QKV projections (mma.sync bf16 3-term) -> fp16 split-head
    dim3 ggrid(DD/128, MROWS/128, 3);   // (8, 32, 3)
    mma_gemm_kernel<<<ggrid, 256>>>(bq, bk, bv, nullptr, 0);

    // 3) tensor-core flash attention (fp16), writes g_Oh/g_Ol split
    dim3 fgrid(SS/64, HH, BB);          // (32, 16, 2)
    flash_tc_kernel<<<fgrid, 128>>>(mask);

    // 4) output projection (mma.sync bf16 3-term) -> fp32 out
    dim3 ogrid(DD/128, MROWS/128, 1);
    mma_gemm_kernel<<<ogrid, 256>>>(bo, nullptr, nullptr, out, 1);
}

// round 6
// speedup vs baseline: 3.1585x; 1.1186x over previous
#include <cuda_runtime.h>
#include <cuda_bf16.h>
#include <cuda_fp16.h>
#include <cstdint>

// Problem constants
#define BB  2
#define SS  2048
#define DD  1024
#define HH  16
#define DK  64
#define MROWS (BB*SS)   // 4096
#define GK  1024

// ---------------------------------------------------------------------------
// Scratch (allocation-free: __device__ globals)
// ---------------------------------------------------------------------------
__device__ __align__(256) __half g_Qf[BB*HH*SS*DK];
__device__ __align__(256) __half g_Kf[BB*HH*SS*DK];
__device__ __align__(256) __half g_Vf[BB*HH*SS*DK];

__device__ __align__(256) __nv_bfloat16 g_qh[MROWS*DD], g_ql[MROWS*DD];
__device__ __align__(256) __nv_bfloat16 g_kh[MROWS*DD], g_kl[MROWS*DD];
__device__ __align__(256) __nv_bfloat16 g_vh[MROWS*DD], g_vl[MROWS*DD];
__device__ __align__(256) __nv_bfloat16 g_Oh[MROWS*DD], g_Ol[MROWS*DD];
__device__ __align__(256) __nv_bfloat16 g_Wqh[DD*DD], g_Wql[DD*DD];
__device__ __align__(256) __nv_bfloat16 g_Wkh[DD*DD], g_Wkl[DD*DD];
__device__ __align__(256) __nv_bfloat16 g_Wvh[DD*DD], g_Wvl[DD*DD];
__device__ __align__(256) __nv_bfloat16 g_Woh[DD*DD], g_Wol[DD*DD];

// ---------------------------------------------------------------------------
// Baseline PTX helpers (sm_80-era: compile for sm_100 non-'a' target)
// ---------------------------------------------------------------------------
__device__ __forceinline__ uint32_t smem_to_u32(const void* p) {
    uint32_t a;
    asm("{ .reg .u64 t; cvta.to.shared.u64 t, %1; cvt.u32.u64 %0, t; }" : "=r"(a) : "l"(p));
    return a;
}
#define CP_ASYNC16(sa, ga) \
    asm volatile("cp.async.cg.shared.global [%0], [%1], 16;" :: "r"(sa), "l"(ga))
#define CP_COMMIT() asm volatile("cp.async.commit_group;" ::: "memory")
#define CP_WAIT(N)  asm volatile("cp.async.wait_group %0;" :: "n"(N) : "memory")

#define LDSM_X4(r0, r1, r2, r3, addr) \
    asm volatile("ldmatrix.sync.aligned.m8n8.x4.shared.b16 {%0,%1,%2,%3}, [%4];" \
        : "=r"(r0), "=r"(r1), "=r"(r2), "=r"(r3) : "r"(addr))
#define LDSM_X4_T(r0, r1, r2, r3, addr) \
    asm volatile("ldmatrix.sync.aligned.m8n8.x4.trans.shared.b16 {%0,%1,%2,%3}, [%4];" \
        : "=r"(r0), "=r"(r1), "=r"(r2), "=r"(r3) : "r"(addr))

#define MMA_BF16(c0, c1, c2, c3, a0, a1, a2, a3, b0, b1) \
    asm volatile("mma.sync.aligned.m16n8k16.row.col.f32.bf16.bf16.f32 " \
        "{%0,%1,%2,%3}, {%4,%5,%6,%7}, {%8,%9}, {%0,%1,%2,%3};" \
        : "+f"(c0), "+f"(c1), "+f"(c2), "+f"(c3) \
        : "r"(a0), "r"(a1), "r"(a2), "r"(a3), "r"(b0), "r"(b1))
#define MMA_F16(c0, c1, c2, c3, a0, a1, a2, a3, b0, b1) \
    asm volatile("mma.sync.aligned.m16n8k16.row.col.f32.f16.f16.f32 " \
        "{%0,%1,%2,%3}, {%4,%5,%6,%7}, {%8,%9}, {%0,%1,%2,%3};" \
        : "+f"(c0), "+f"(c1), "+f"(c2), "+f"(c3) \
        : "r"(a0), "r"(a1), "r"(a2), "r"(a3), "r"(b0), "r"(b1))

__device__ __forceinline__ uint32_t pack_half2(float lo, float hi) {
    __half2 h = __floats2half2_rn(lo, hi);
    return *(uint32_t*)&h;
}

// ---------------------------------------------------------------------------
// Fused fp32 -> bf16 hi/lo split conversion: blockIdx.y selects the tensor.
// ---------------------------------------------------------------------------
__global__ __launch_bounds__(256)
void conv_all_kernel(const float* __restrict__ q, const float* __restrict__ k,
                     const float* __restrict__ v,
                     const float* __restrict__ Wq, const float* __restrict__ Wk,
                     const float* __restrict__ Wv, const float* __restrict__ Wo)
{
    int which = blockIdx.y;
    const float* src;
    __nv_bfloat16 *hi, *lo;
    int n4;
    const int NIN4 = MROWS*DD/4, NW4 = DD*DD/4;
    switch (which) {
        case 0: src = q;  hi = g_qh;  lo = g_ql;  n4 = NIN4; break;
        case 1: src = k;  hi = g_kh;  lo = g_kl;  n4 = NIN4; break;
        case 2: src = v;  hi = g_vh;  lo = g_vl;  n4 = NIN4; break;
        case 3: src = Wq; hi = g_Wqh; lo = g_Wql; n4 = NW4;  break;
        case 4: src = Wk; hi = g_Wkh; lo = g_Wkl; n4 = NW4;  break;
        case 5: src = Wv; hi = g_Wvh; lo = g_Wvl; n4 = NW4;  break;
        default:src = Wo; hi = g_Woh; lo = g_Wol; n4 = NW4;  break;
    }
    int i = blockIdx.x * blockDim.x + threadIdx.x;
    if (i >= n4) return;
    float4 vv = ((const float4*)src)[i];
    float f[4] = {vv.x, vv.y, vv.z, vv.w};
    ushort4 hs, ls;
    unsigned short* hp = &hs.x;
    unsigned short* lp = &ls.x;
    #pragma unroll
    for (int j = 0; j < 4; j++) {
        __nv_bfloat16 h = __float2bfloat16(f[j]);
        __nv_bfloat16 l = __float2bfloat16(f[j] - __bfloat162float(h));
        hp[j] = __bfloat16_as_ushort(h);
        lp[j] = __bfloat16_as_ushort(l);
    }
    ((ushort4*)hi)[i] = hs;
    ((ushort4*)lo)[i] = ls;
}

// ---------------------------------------------------------------------------
// Tensor-core GEMM (mma.sync bf16, 3-term hi/lo split, effective K=3072).
// 128x128 CTA tile, 8 warps (2x4), 64x32 warp tile, BK=32 per stage.
// 3-stage cp.async ring, ONE __syncthreads per stage (CUTLASS sm80 schedule).
// ---------------------------------------------------------------------------
#define BKS 32
#define BKP 40
#define NSTAGE 96                   // 3 * (1024/32)
#define TILE_ELEMS (128*BKP)        // 5120 bf16
#define TILE_BYTES (TILE_ELEMS*2)   // 10240 B
#define SLOT_BYTES (2*TILE_BYTES)   // A+B per stage
#define GEMM_SMEM  (3*SLOT_BYTES)   // 61440 B

__global__ __launch_bounds__(256)
void mma_gemm_kernel(const float* __restrict__ bias0, const float* __restrict__ bias1,
                     const float* __restrict__ bias2, float* __restrict__ Yext, int is_out)
{
    extern __shared__ char smem_raw[];
    uint32_t sbase = smem_to_u32(smem_raw);

    int tid = threadIdx.x, wid = tid >> 5, lane = tid & 31;
    int warp_m = wid >> 2;          // 0..1
    int warp_n = wid & 3;           // 0..3
    int m0 = blockIdx.y * 128, n0 = blockIdx.x * 128;
    int z = blockIdx.z;

    const __nv_bfloat16 *Ah, *Al, *Bh, *Bl;
    const float* bias;
    if (is_out)      { Ah = g_Oh; Al = g_Ol; Bh = g_Woh; Bl = g_Wol; bias = bias0; }
    else if (z == 0) { Ah = g_qh; Al = g_ql; Bh = g_Wqh; Bl = g_Wql; bias = bias0; }
    else if (z == 1) { Ah = g_kh; Al = g_kl; Bh = g_Wkh; Bl = g_Wkl; bias = bias1; }
    else             { Ah = g_vh; Al = g_vl; Bh = g_Wvh; Bl = g_Wvl; bias = bias2; }

    int lrow = tid >> 1;
    int lc0  = (tid & 1) * 2;

    float c[4][4][4];
    #pragma unroll
    for (int i = 0; i < 4; i++)
        #pragma unroll
        for (int j = 0; j < 4; j++)
            #pragma unroll
            for (int r = 0; r < 4; r++) c[i][j][r] = 0.f;

    auto load_stage = [&](int s, int slot) {
        int p   = s >> 5;
        int kin = (s & 31) * BKS;
        const __nv_bfloat16* Ap = (p == 2) ? Al : Ah;
        const __nv_bfloat16* Bp = (p == 1) ? Bl : Bh;
        uint32_t sA = sbase + slot * SLOT_BYTES;
        uint32_t sB = sA + TILE_BYTES;
        #pragma unroll
        for (int i = 0; i < 2; i++) {
            int cc = lc0 + i;
            uint32_t soff = (uint32_t)(lrow * BKP + cc * 8) * 2;
            const __nv_bfloat16* ga = Ap + (size_t)(m0 + lrow) * GK + kin + cc * 8;
            const __nv_bfloat16* gb = Bp + (size_t)(n0 + lrow) * GK + kin + cc * 8;
            CP_ASYNC16(sA + soff, ga);
            CP_ASYNC16(sB + soff, gb);
        }
    };

    // prologue: stages 0 and 1 in flight
    load_stage(0, 0); CP_COMMIT();
    load_stage(1, 1); CP_COMMIT();
    CP_WAIT(1);
    __syncthreads();        // stage 0 ready for everyone

    for (int s = 0; s < NSTAGE; s++) {
        int slot = s % 3;
        // issue load for stage s+2 into the slot freed at the end of iter s-1
        if (s + 2 < NSTAGE) { load_stage(s + 2, (s + 2) % 3); CP_COMMIT(); }

        uint32_t sA = sbase + slot * SLOT_BYTES;
        uint32_t sB = sA + TILE_BYTES;
        #pragma unroll
        for (int ks = 0; ks < BKS; ks += 16) {
            uint32_t a[4][4], bfr[4][2];
            #pragma unroll
            for (int fm = 0; fm < 4; fm++) {
                int r   = warp_m * 64 + fm * 16 + (lane & 15);
                int col = ks + ((lane >> 4) << 3);
                uint32_t addr = sA + (uint32_t)(r * BKP + col) * 2;
                LDSM_X4(a[fm][0], a[fm][1], a[fm][2], a[fm][3], addr);
            }
            #pragma unroll
            for (int gp = 0; gp < 2; gp++) {
                int r   = warp_n * 32 + gp * 16 + ((lane >> 4) << 3) + (lane & 7);
                int col = ks + (((lane >> 3) & 1) << 3);
                uint32_t addr = sB + (uint32_t)(r * BKP + col) * 2;
                uint32_t r0, r1, r2, r3;
                LDSM_X4(r0, r1, r2, r3, addr);
                bfr[gp*2][0] = r0; bfr[gp*2][1] = r1;
                bfr[gp*2+1][0] = r2; bfr[gp*2+1][1] = r3;
            }
            #pragma unroll
            for (int fm = 0; fm < 4; fm++)
                #pragma unroll
                for (int fn = 0; fn < 4; fn++)
                    MMA_BF16(c[fm][fn][0], c[fm][fn][1], c[fm][fn][2], c[fm][fn][3],
                             a[fm][0], a[fm][1], a[fm][2], a[fm][3],
                             bfr[fn][0], bfr[fn][1]);
        }

        if (s + 2 < NSTAGE) CP_WAIT(1); else CP_WAIT(0);
        __syncthreads();    // stage s+1 ready; slot (s%3) free for iter s+1's issue
    }

    // epilogue: C frag mapping m16n8: row = lane/4 (+8), col = 2*(lane%4)
    int grp = lane >> 2, q4 = (lane & 3) * 2;
    #pragma unroll
    for (int fm = 0; fm < 4; fm++) {
        #pragma unroll
        for (int fn = 0; fn < 4; fn++) {
            int n = n0 + warp_n * 32 + fn * 8 + q4;
            float b0 = bias[n], b1 = bias[n + 1];
            #pragma unroll
            for (int half = 0; half < 2; half++) {
                int m = m0 + warp_m * 64 + fm * 16 + grp + half * 8;
                float v0 = c[fm][fn][half*2 + 0] + b0;
                float v1 = c[fm][fn][half*2 + 1] + b1;
                if (is_out) {
                    float2* dst = (float2*)&Yext[(size_t)m * DD + n];
                    *dst = make_float2(v0, v1);
                } else {
                    __half* Yf = (z == 0) ? g_Qf : (z == 1) ? g_Kf : g_Vf;
                    int bidx = m >> 11, srow = m & (SS - 1);
                    int h = n >> 6, dk = n & 63;
                    __half2 hv = __floats2half2_rn(v0, v1);
                    *(__half2*)&Yf[(((size_t)(bidx*HH + h) * SS + srow) * DK) + dk] = hv;
                }
            }
        }
    }
}

// ---------------------------------------------------------------------------
// Tensor-core flash attention (fp16 mma.sync, fp32 accum + softmax).
// CTA = (b, h, 64-query tile), 128 threads / 4 warps.  [unchanged from R5]
// ---------------------------------------------------------------------------
#define LQ 72

__global__ __launch_bounds__(128)
void flash_tc_kernel(const int* __restrict__ mask)
{
    __shared__ __half Qs[64*LQ];
    __shared__ __half Ks[2][64*LQ];
    __shared__ __half Vs[2][64*LQ];
    __shared__ int    Ms[2][64];

    int tid = threadIdx.x, w = tid >> 5, t = tid & 31;
    int q0 = blockIdx.x * 64;
    int h  = blockIdx.y;
    int b  = blockIdx.z;
    size_t base = (size_t)(b*HH + h) * SS * DK;

    uint32_t sQ  = smem_to_u32(Qs);
    uint32_t sK[2] = { smem_to_u32(Ks[0]), smem_to_u32(Ks[1]) };
    uint32_t sV[2] = { smem_to_u32(Vs[0]), smem_to_u32(Vs[1]) };
    uint32_t sM[2] = { smem_to_u32(Ms[0]), smem_to_u32(Ms[1]) };

    int lrow = tid >> 1, lhalf = tid & 1;

    {
        const uint4* src = (const uint4*)(g_Qf + base + (size_t)(q0 + lrow) * DK + lhalf * 32);
        uint4* dst = (uint4*)&Qs[lrow * LQ + lhalf * 32];
        #pragma unroll
        for (int i = 0; i < 4; i++) dst[i] = src[i];
    }
    auto load_stage = [&](int ti, int bn) {
        const __half* gk = g_Kf + base + (size_t)(ti*64 + lrow) * DK + lhalf * 32;
        const __half* gv = g_Vf + base + (size_t)(ti*64 + lrow) * DK + lhalf * 32;
        uint32_t so = (uint32_t)(lrow * LQ + lhalf * 32) * 2;
        #pragma unroll
        for (int ccc = 0; ccc < 4; ccc++) {
            CP_ASYNC16(sK[bn] + so + ccc*16, gk + ccc*8);
            CP_ASYNC16(sV[bn] + so + ccc*16, gv + ccc*8);
        }
        if (tid < 16) CP_ASYNC16(sM[bn] + tid*16, mask + b*SS + ti*64 + tid*4);
    };
    load_stage(0, 0);
    CP_COMMIT();
    __syncthreads();

    uint32_t qa[4][4];
    #pragma unroll
    for (int kt = 0; kt < 4; kt++) {
        uint32_t addr = sQ + (uint32_t)((w*16 + (t & 15)) * LQ + kt*16 + ((t >> 4) << 3)) * 2;
        LDSM_X4(qa[kt][0], qa[kt][1], qa[kt][2], qa[kt][3], addr);
    }

    float o[8][4];
    #pragma unroll
    for (int n = 0; n < 8; n++)
        #pragma unroll
        for (int i = 0; i < 4; i++) o[n][i] = 0.f;
    float m0r = -3.0e38f, m1r = -3.0e38f, l0 = 0.f, l1 = 0.f;

    int buf = 0;
    for (int ti = 0; ti < SS/64; ti++) {
        int nb = buf ^ 1;
        if (ti + 1 < SS/64) {
            load_stage(ti + 1, nb);
            CP_COMMIT();
            CP_WAIT(1);
        } else {
            CP_WAIT(0);
        }
        __syncthreads();

        float c[8][4];
        #pragma unroll
        for (int n = 0; n < 8; n++)
            #pragma unroll
            for (int i = 0; i < 4; i++) c[n][i] = 0.f;

        #pragma unroll
        for (int kt = 0; kt < 4; kt++) {
            #pragma unroll
            for (int np = 0; np < 4; np++) {
                uint32_t r0, r1, r2, r3;
                uint32_t addr = sK[buf] + (uint32_t)((np*16 + ((t >> 4) << 3) + (t & 7)) * LQ
                                                      + kt*16 + (((t >> 3) & 1) << 3)) * 2;
                LDSM_X4(r0, r1, r2, r3, addr);
                MMA_F16(c[2*np][0], c[2*np][1], c[2*np][2], c[2*np][3],
                        qa[kt][0], qa[kt][1], qa[kt][2], qa[kt][3], r0, r1);
                MMA_F16(c[2*np+1][0], c[2*np+1][1], c[2*np+1][2], c[2*np+1][3],
                        qa[kt][0], qa[kt][1], qa[kt][2], qa[kt][3], r2, r3);
            }
        }

        #pragma unroll
        for (int n = 0; n < 8; n++) {
            int cb = n*8 + (t & 3)*2;
            int mb0 = Ms[buf][cb], mb1 = Ms[buf][cb + 1];
            c[n][0] = mb0 ? c[n][0]*0.125f : -1.0e9f;
            c[n][2] = mb0 ? c[n][2]*0.125f : -1.0e9f;
            c[n][1] = mb1 ? c[n][1]*0.125f : -1.0e9f;
            c[n][3] = mb1 ? c[n][3]*0.125f : -1.0e9f;
        }

        float tm0 = -3.0e38f, tm1 = -3.0e38f;
        #pragma unroll
        for (int n = 0; n < 8; n++) {
            tm0 = fmaxf(tm0, fmaxf(c[n][0], c[n][1]));
            tm1 = fmaxf(tm1, fmaxf(c[n][2], c[n][3]));
        }
        tm0 = fmaxf(tm0, __shfl_xor_sync(0xffffffffu, tm0, 1));
        tm0 = fmaxf(tm0, __shfl_xor_sync(0xffffffffu, tm0, 2));
        tm1 = fmaxf(tm1, __shfl_xor_sync(0xffffffffu, tm1, 1));
        tm1 = fmaxf(tm1, __shfl_xor_sync(0xffffffffu, tm1, 2));

        float mn0 = fmaxf(m0r, tm0), mn1 = fmaxf(m1r, tm1);
        float al0 = __expf(m0r - mn0), al1 = __expf(m1r - mn1);
        float ts0 = 0.f, ts1 = 0.f;
        #pragma unroll
        for (int n = 0; n < 8; n++) {
            c[n][0] = __expf(c[n][0] - mn0); ts0 += c[n][0];
            c[n][1] = __expf(c[n][1] - mn0); ts0 += c[n][1];
            c[n][2] = __expf(c[n][2] - mn1); ts1 += c[n][2];
            c[n][3] = __expf(c[n][3] - mn1); ts1 += c[n][3];
        }
        ts0 += __shfl_xor_sync(0xffffffffu, ts0, 1);
        ts0 += __shfl_xor_sync(0xffffffffu, ts0, 2);
        ts1 += __shfl_xor_sync(0xffffffffu, ts1, 1);
        ts1 += __shfl_xor_sync(0xffffffffu, ts1, 2);
        l0 = l0*al0 + ts0; l1 = l1*al1 + ts1;
        m0r = mn0; m1r = mn1;
        #pragma unroll
        for (int n = 0; n < 8; n++) {
            o[n][0] *= al0; o[n][1] *= al0;
            o[n][2] *= al1; o[n][3] *= al1;
        }

        uint32_t pa[4][4];
        #pragma unroll
        for (int kt = 0; kt < 4; kt++) {
            pa[kt][0] = pack_half2(c[2*kt][0],   c[2*kt][1]);
            pa[kt][1] = pack_half2(c[2*kt][2],   c[2*kt][3]);
            pa[kt][2] = pack_half2(c[2*kt+1][0], c[2*kt+1][1]);
            pa[kt][3] = pack_half2(c[2*kt+1][2], c[2*kt+1][3]);
        }

        #pragma unroll
        for (int kt = 0; kt < 4; kt++) {
            #pragma unroll
            for (int nh = 0; nh < 4; nh++) {
                uint32_t r0, r1, r2, r3;
                uint32_t addr = sV[buf] + (uint32_t)((kt*16 + (t & 15)) * LQ
                                                      + nh*16 + ((t >> 4) << 3)) * 2;
                LDSM_X4_T(r0, r1, r2, r3, addr);
                MMA_F16(o[2*nh][0], o[2*nh][1], o[2*nh][2], o[2*nh][3],
                        pa[kt][0], pa[kt][1], pa[kt][2], pa[kt][3], r0, r1);
                MMA_F16(o[2*nh+1][0], o[2*nh+1][1], o[2*nh+1][2], o[2*nh+1][3],
                        pa[kt][0], pa[kt][1], pa[kt][2], pa[kt][3], r2, r3);
            }
        }

        __syncthreads();
        buf = nb;
    }

    float inv0 = (l0 > 0.f) ? (1.0f / l0) : 0.f;
    float inv1 = (l1 > 0.f) ? (1.0f / l1) : 0.f;
    int qr0 = q0 + w*16 + (t >> 2), qr1 = qr0 + 8;
    int dbase = (t & 3) * 2;
    #pragma unroll
    for (int n = 0; n < 8; n++) {
        int d = n*8 + dbase;
        size_t i0 = ((size_t)b*SS + qr0) * DD + h*DK + d;
        size_t i1 = ((size_t)b*SS + qr1) * DD + h*DK + d;
        float v0 = o[n][0]*inv0, v1 = o[n][1]*inv0;
        float v2 = o[n][2]*inv1, v3 = o[n][3]*inv1;
        __nv_bfloat16 h0 = __float2bfloat16(v0), h1 = __float2bfloat16(v1);
        __nv_bfloat16 h2 = __float2bfloat16(v2), h3 = __float2bfloat16(v3);
        *(__nv_bfloat162*)&g_Oh[i0] = __nv_bfloat162(h0, h1);
        *(__nv_bfloat162*)&g_Ol[i0] = __nv_bfloat162(
            __float2bfloat16(v0 - __bfloat162float(h0)),
            __float2bfloat16(v1 - __bfloat162float(h1)));
        *(__nv_bfloat162*)&g_Oh[i1] = __nv_bfloat162(h2, h3);
        *(__nv_bfloat162*)&g_Ol[i1] = __nv_bfloat162(
            __float2bfloat16(v2 - __bfloat162float(h2)),
            __float2bfloat16(v3 - __bfloat162float(h3)));
    }
}

// ---------------------------------------------------------------------------
extern "C" void kernel_launch(void* const* d_in, const int* in_sizes, int n_in,
                              void* d_out, int out_size)
{
    const float* q    = (const float*)d_in[0];
    const float* k    = (const float*)d_in[1];
    const float* v    = (const float*)d_in[2];
    const int*   mask = (const int*)  d_in[3];
    const float* Wq   = (const float*)d_in[4];
    const float* bq   = (const float*)d_in[5];
    const float* Wk   = (const float*)d_in[6];
    const float* bk   = (const float*)d_in[7];
    const float* Wv   = (const float*)d_in[8];
    const float* bv   = (const float*)d_in[9];
    const float* Wo   = (const float*)d_in[10];
    const float* bo   = (const float*)d_in[11];
    float* out = (float*)d_out;

    // opt-in to >48KB dynamic smem for the GEMM (idempotent, capture-safe)
    cudaFuncSetAttribute(mma_gemm_kernel,
                         cudaFuncAttributeMaxDynamicSharedMemorySize, GEMM_SMEM);

    // 1) fused fp32 -> bf16 hi/lo conversions (one launch, 7 tensors)
    const int NIN4 = MROWS*DD/4;
    dim3 cgrid((NIN4 + 255) / 256, 7);
    conv_all_kernel<<<cgrid, 256>>>(q, k, v, Wq, Wk, Wv, Wo);

    // 2) fused QKV projections (mma.sync bf16 3-term) -> fp16 split-head
    dim3 ggrid(DD/128, MROWS/128, 3);   // (8, 32, 3)
    mma_gemm_kernel<<<ggrid, 256, GEMM_SMEM>>>(bq, bk, bv, nullptr, 0);

    // 3) tensor-core flash attention (fp16), writes g_Oh/g_Ol split
    dim3 fgrid(SS/64, HH, BB);          // (32, 16, 2)
    flash_tc_kernel<<<fgrid, 128>>>(mask);

    // 4) output projection (mma.sync bf16 3-term) -> fp32 out
    dim3 ogrid(DD/128, MROWS/128, 1);
    mma_gemm_kernel<<<ogrid, 256, GEMM_SMEM>>>(bo, nullptr, nullptr, out, 1);
}

// round 7
// speedup vs baseline: 5.6190x; 1.7790x over previous
#include <cuda_runtime.h>
#include <cuda_bf16.h>
#include <cuda_fp16.h>
#include <cstdint>

// Problem constants
#define BB  2
#define SS  2048
#define DD  1024
#define HH  16
#define DK  64
#define MROWS (BB*SS)   // 4096
#define GK  1024

// ---------------------------------------------------------------------------
// Scratch (allocation-free: __device__ globals) — all fp16 now
// ---------------------------------------------------------------------------
// GEMM inputs
__device__ __align__(256) __half g_qf[MROWS*DD], g_kf[MROWS*DD], g_vf[MROWS*DD];
__device__ __align__(256) __half g_Wqf[DD*DD], g_Wkf[DD*DD], g_Wvf[DD*DD], g_Wof[DD*DD];
// split-head Q/K/V for flash
__device__ __align__(256) __half g_Qf[BB*HH*SS*DK];
__device__ __align__(256) __half g_Kf[BB*HH*SS*DK];
__device__ __align__(256) __half g_Vf[BB*HH*SS*DK];
// attention output [B,S,D] (A operand of out-projection)
__device__ __align__(256) __half g_Of[MROWS*DD];

// ---------------------------------------------------------------------------
// Baseline PTX helpers (sm_80-era: compile for sm_100 non-'a' target)
// ---------------------------------------------------------------------------
__device__ __forceinline__ uint32_t smem_to_u32(const void* p) {
    uint32_t a;
    asm("{ .reg .u64 t; cvta.to.shared.u64 t, %1; cvt.u32.u64 %0, t; }" : "=r"(a) : "l"(p));
    return a;
}
#define CP_ASYNC16(sa, ga) \
    asm volatile("cp.async.cg.shared.global [%0], [%1], 16;" :: "r"(sa), "l"(ga))
#define CP_COMMIT() asm volatile("cp.async.commit_group;" ::: "memory")
#define CP_WAIT(N)  asm volatile("cp.async.wait_group %0;" :: "n"(N) : "memory")

#define LDSM_X4(r0, r1, r2, r3, addr) \
    asm volatile("ldmatrix.sync.aligned.m8n8.x4.shared.b16 {%0,%1,%2,%3}, [%4];" \
        : "=r"(r0), "=r"(r1), "=r"(r2), "=r"(r3) : "r"(addr))
#define LDSM_X4_T(r0, r1, r2, r3, addr) \
    asm volatile("ldmatrix.sync.aligned.m8n8.x4.trans.shared.b16 {%0,%1,%2,%3}, [%4];" \
        : "=r"(r0), "=r"(r1), "=r"(r2), "=r"(r3) : "r"(addr))

#define MMA_F16(c0, c1, c2, c3, a0, a1, a2, a3, b0, b1) \
    asm volatile("mma.sync.aligned.m16n8k16.row.col.f32.f16.f16.f32 " \
        "{%0,%1,%2,%3}, {%4,%5,%6,%7}, {%8,%9}, {%0,%1,%2,%3};" \
        : "+f"(c0), "+f"(c1), "+f"(c2), "+f"(c3) \
        : "r"(a0), "r"(a1), "r"(a2), "r"(a3), "r"(b0), "r"(b1))

__device__ __forceinline__ uint32_t pack_half2(float lo, float hi) {
    __half2 h = __floats2half2_rn(lo, hi);
    return *(uint32_t*)&h;
}

// ---------------------------------------------------------------------------
// Fused fp32 -> fp16 conversion: blockIdx.y selects the tensor.
// ---------------------------------------------------------------------------
__global__ __launch_bounds__(256)
void conv_all_kernel(const float* __restrict__ q, const float* __restrict__ k,
                     const float* __restrict__ v,
                     const float* __restrict__ Wq, const float* __restrict__ Wk,
                     const float* __restrict__ Wv, const float* __restrict__ Wo)
{
    int which = blockIdx.y;
    const float* src;
    __half* dst;
    int n4;
    const int NIN4 = MROWS*DD/4, NW4 = DD*DD/4;
    switch (which) {
        case 0: src = q;  dst = g_qf;  n4 = NIN4; break;
        case 1: src = k;  dst = g_kf;  n4 = NIN4; break;
        case 2: src = v;  dst = g_vf;  n4 = NIN4; break;
        case 3: src = Wq; dst = g_Wqf; n4 = NW4;  break;
        case 4: src = Wk; dst = g_Wkf; n4 = NW4;  break;
        case 5: src = Wv; dst = g_Wvf; n4 = NW4;  break;
        default:src = Wo; dst = g_Wof; n4 = NW4;  break;
    }
    int i = blockIdx.x * blockDim.x + threadIdx.x;
    if (i >= n4) return;
    float4 vv = ((const float4*)src)[i];
    __half2 h0 = __floats2half2_rn(vv.x, vv.y);
    __half2 h1 = __floats2half2_rn(vv.z, vv.w);
    uint2 pk = make_uint2(*(uint32_t*)&h0, *(uint32_t*)&h1);
    ((uint2*)dst)[i] = pk;
}

// ---------------------------------------------------------------------------
// Tensor-core GEMM (mma.sync fp16, single term, K=1024).
// 128x128 CTA tile, 8 warps (2x4), 64x32 warp tile, BK=32 per stage.
// 3-stage cp.async ring, ONE __syncthreads per stage.
// ---------------------------------------------------------------------------
#define BKS 32
#define BKP 40
#define NSTAGE 32                   // 1024/32
#define TILE_ELEMS (128*BKP)        // 5120 half
#define TILE_BYTES (TILE_ELEMS*2)   // 10240 B
#define SLOT_BYTES (2*TILE_BYTES)   // A+B per stage
#define GEMM_SMEM  (3*SLOT_BYTES)   // 61440 B

__global__ __launch_bounds__(256)
void mma_gemm_kernel(const float* __restrict__ bias0, const float* __restrict__ bias1,
                     const float* __restrict__ bias2, float* __restrict__ Yext, int is_out)
{
    extern __shared__ char smem_raw[];
    uint32_t sbase = smem_to_u32(smem_raw);

    int tid = threadIdx.x, wid = tid >> 5, lane = tid & 31;
    int warp_m = wid >> 2;          // 0..1
    int warp_n = wid & 3;           // 0..3
    int m0 = blockIdx.y * 128, n0 = blockIdx.x * 128;
    int z = blockIdx.z;

    const __half *A, *B;
    const float* bias;
    if (is_out)      { A = g_Of; B = g_Wof; bias = bias0; }
    else if (z == 0) { A = g_qf; B = g_Wqf; bias = bias0; }
    else if (z == 1) { A = g_kf; B = g_Wkf; bias = bias1; }
    else             { A = g_vf; B = g_Wvf; bias = bias2; }

    int lrow = tid >> 1;
    int lc0  = (tid & 1) * 2;

    float c[4][4][4];
    #pragma unroll
    for (int i = 0; i < 4; i++)
        #pragma unroll
        for (int j = 0; j < 4; j++)
            #pragma unroll
            for (int r = 0; r < 4; r++) c[i][j][r] = 0.f;

    auto load_stage = [&](int s, int slot) {
        int kin = s * BKS;
        uint32_t sA = sbase + slot * SLOT_BYTES;
        uint32_t sB = sA + TILE_BYTES;
        #pragma unroll
        for (int i = 0; i < 2; i++) {
            int cc = lc0 + i;
            uint32_t soff = (uint32_t)(lrow * BKP + cc * 8) * 2;
            const __half* ga = A + (size_t)(m0 + lrow) * GK + kin + cc * 8;
            const __half* gb = B + (size_t)(n0 + lrow) * GK + kin + cc * 8;
            CP_ASYNC16(sA + soff, ga);
            CP_ASYNC16(sB + soff, gb);
        }
    };

    load_stage(0, 0); CP_COMMIT();
    load_stage(1, 1); CP_COMMIT();
    CP_WAIT(1);
    __syncthreads();

    for (int s = 0; s < NSTAGE; s++) {
        int slot = s % 3;
        if (s + 2 < NSTAGE) { load_stage(s + 2, (s + 2) % 3); CP_COMMIT(); }

        uint32_t sA = sbase + slot * SLOT_BYTES;
        uint32_t sB = sA + TILE_BYTES;
        #pragma unroll
        for (int ks = 0; ks < BKS; ks += 16) {
            uint32_t a[4][4], bfr[4][2];
            #pragma unroll
            for (int fm = 0; fm < 4; fm++) {
                int r   = warp_m * 64 + fm * 16 + (lane & 15);
                int col = ks + ((lane >> 4) << 3);
                uint32_t addr = sA + (uint32_t)(r * BKP + col) * 2;
                LDSM_X4(a[fm][0], a[fm][1], a[fm][2], a[fm][3], addr);
            }
            #pragma unroll
            for (int gp = 0; gp < 2; gp++) {
                int r   = warp_n * 32 + gp * 16 + ((lane >> 4) << 3) + (lane & 7);
                int col = ks + (((lane >> 3) & 1) << 3);
                uint32_t addr = sB + (uint32_t)(r * BKP + col) * 2;
                uint32_t r0, r1, r2, r3;
                LDSM_X4(r0, r1, r2, r3, addr);
                bfr[gp*2][0] = r0; bfr[gp*2][1] = r1;
                bfr[gp*2+1][0] = r2; bfr[gp*2+1][1] = r3;
            }
            #pragma unroll
            for (int fm = 0; fm < 4; fm++)
                #pragma unroll
                for (int fn = 0; fn < 4; fn++)
                    MMA_F16(c[fm][fn][0], c[fm][fn][1], c[fm][fn][2], c[fm][fn][3],
                            a[fm][0], a[fm][1], a[fm][2], a[fm][3],
                            bfr[fn][0], bfr[fn][1]);
        }

        if (s + 2 < NSTAGE) CP_WAIT(1); else CP_WAIT(0);
        __syncthreads();
    }

    // epilogue: C frag mapping m16n8: row = lane/4 (+8), col = 2*(lane%4)
    int grp = lane >> 2, q4 = (lane & 3) * 2;
    #pragma unroll
    for (int fm = 0; fm < 4; fm++) {
        #pragma unroll
        for (int fn = 0; fn < 4; fn++) {
            int n = n0 + warp_n * 32 + fn * 8 + q4;
            float b0 = bias[n], b1 = bias[n + 1];
            #pragma unroll
            for (int half = 0; half < 2; half++) {
                int m = m0 + warp_m * 64 + fm * 16 + grp + half * 8;
                float v0 = c[fm][fn][half*2 + 0] + b0;
                float v1 = c[fm][fn][half*2 + 1] + b1;
                if (is_out) {
                    float2* dst = (float2*)&Yext[(size_t)m * DD + n];
                    *dst = make_float2(v0, v1);
                } else {
                    __half* Yf = (z == 0) ? g_Qf : (z == 1) ? g_Kf : g_Vf;
                    int bidx = m >> 11, srow = m & (SS - 1);
                    int h = n >> 6, dk = n & 63;
                    __half2 hv = __floats2half2_rn(v0, v1);
                    *(__half2*)&Yf[(((size_t)(bidx*HH + h) * SS + srow) * DK) + dk] = hv;
                }
            }
        }
    }
}

// ---------------------------------------------------------------------------
// Tensor-core flash attention (fp16 mma.sync, fp32 accum + softmax).
// CTA = (b, h, 64-query tile), 128 threads / 4 warps.
// Epilogue writes fp16 O into g_Of [B,S,D].
// ---------------------------------------------------------------------------
#define LQ 72

__global__ __launch_bounds__(128)
void flash_tc_kernel(const int* __restrict__ mask)
{
    __shared__ __half Qs[64*LQ];
    __shared__ __half Ks[2][64*LQ];
    __shared__ __half Vs[2][64*LQ];
    __shared__ int    Ms[2][64];

    int tid = threadIdx.x, w = tid >> 5, t = tid & 31;
    int q0 = blockIdx.x * 64;
    int h  = blockIdx.y;
    int b  = blockIdx.z;
    size_t base = (size_t)(b*HH + h) * SS * DK;

    uint32_t sQ  = smem_to_u32(Qs);
    uint32_t sK[2] = { smem_to_u32(Ks[0]), smem_to_u32(Ks[1]) };
    uint32_t sV[2] = { smem_to_u32(Vs[0]), smem_to_u32(Vs[1]) };
    uint32_t sM[2] = { smem_to_u32(Ms[0]), smem_to_u32(Ms[1]) };

    int lrow = tid >> 1, lhalf = tid & 1;

    {
        const uint4* src = (const uint4*)(g_Qf + base + (size_t)(q0 + lrow) * DK + lhalf * 32);
        uint4* dst = (uint4*)&Qs[lrow * LQ + lhalf * 32];
        #pragma unroll
        for (int i = 0; i < 4; i++) dst[i] = src[i];
    }
    auto load_stage = [&](int ti, int bn) {
        const __half* gk = g_Kf + base + (size_t)(ti*64 + lrow) * DK + lhalf * 32;
        const __half* gv = g_Vf + base + (size_t)(ti*64 + lrow) * DK + lhalf * 32;
        uint32_t so = (uint32_t)(lrow * LQ + lhalf * 32) * 2;
        #pragma unroll
        for (int ccc = 0; ccc < 4; ccc++) {
            CP_ASYNC16(sK[bn] + so + ccc*16, gk + ccc*8);
            CP_ASYNC16(sV[bn] + so + ccc*16, gv + ccc*8);
        }
        if (tid < 16) CP_ASYNC16(sM[bn] + tid*16, mask + b*SS + ti*64 + tid*4);
    };
    load_stage(0, 0);
    CP_COMMIT();
    __syncthreads();

    uint32_t qa[4][4];
    #pragma unroll
    for (int kt = 0; kt < 4; kt++) {
        uint32_t addr = sQ + (uint32_t)((w*16 + (t & 15)) * LQ + kt*16 + ((t >> 4) << 3)) * 2;
        LDSM_X4(qa[kt][0], qa[kt][1], qa[kt][2], qa[kt][3], addr);
    }

    float o[8][4];
    #pragma unroll
    for (int n = 0; n < 8; n++)
        #pragma unroll
        for (int i = 0; i < 4; i++) o[n][i] = 0.f;
    float m0r = -3.0e38f, m1r = -3.0e38f, l0 = 0.f, l1 = 0.f;

    int buf = 0;
    for (int ti = 0; ti < SS/64; ti++) {
        int nb = buf ^ 1;
        if (ti + 1 < SS/64) {
            load_stage(ti + 1, nb);
            CP_COMMIT();
            CP_WAIT(1);
        } else {
            CP_WAIT(0);
        }
        __syncthreads();

        float c[8][4];
        #pragma unroll
        for (int n = 0; n < 8; n++)
            #pragma unroll
            for (int i = 0; i < 4; i++) c[n][i] = 0.f;

        #pragma unroll
        for (int kt = 0; kt < 4; kt++) {
            #pragma unroll
            for (int np = 0; np < 4; np++) {
                uint32_t r0, r1, r2, r3;
                uint32_t addr = sK[buf] + (uint32_t)((np*16 + ((t >> 4) << 3) + (t & 7)) * LQ
                                                      + kt*16 + (((t >> 3) & 1) << 3)) * 2;
                LDSM_X4(r0, r1, r2, r3, addr);
                MMA_F16(c[2*np][0], c[2*np][1], c[2*np][2], c[2*np][3],
                        qa[kt][0], qa[kt][1], qa[kt][2], qa[kt][3], r0, r1);
                MMA_F16(c[2*np+1][0], c[2*np+1][1], c[2*np+1][2], c[2*np+1][3],
                        qa[kt][0], qa[kt][1], qa[kt][2], qa[kt][3], r2, r3);
            }
        }

        #pragma unroll
        for (int n = 0; n < 8; n++) {
            int cb = n*8 + (t & 3)*2;
            int mb0 = Ms[buf][cb], mb1 = Ms[buf][cb + 1];
            c[n][0] = mb0 ? c[n][0]*0.125f : -1.0e9f;
            c[n][2] = mb0 ? c[n][2]*0.125f : -1.0e9f;
            c[n][1] = mb1 ? c[n][1]*0.125f : -1.0e9f;
            c[n][3] = mb1 ? c[n][3]*0.125f : -1.0e9f;
        }

        float tm0 = -3.0e38f, tm1 = -3.0e38f;
        #pragma unroll
        for (int n = 0; n < 8; n++) {
            tm0 = fmaxf(tm0, fmaxf(c[n][0], c[n][1]));
            tm1 = fmaxf(tm1, fmaxf(c[n][2], c[n][3]));
        }
        tm0 = fmaxf(tm0, __shfl_xor_sync(0xffffffffu, tm0, 1));
        tm0 = fmaxf(tm0, __shfl_xor_sync(0xffffffffu, tm0, 2));
        tm1 = fmaxf(tm1, __shfl_xor_sync(0xffffffffu, tm1, 1));
        tm1 = fmaxf(tm1, __shfl_xor_sync(0xffffffffu, tm1, 2));

        float mn0 = fmaxf(m0r, tm0), mn1 = fmaxf(m1r, tm1);
        float al0 = __expf(m0r - mn0), al1 = __expf(m1r - mn1);
        float ts0 = 0.f, ts1 = 0.f;
        #pragma unroll
        for (int n = 0; n < 8; n++) {
            c[n][0] = __expf(c[n][0] - mn0); ts0 += c[n][0];
            c[n][1] = __expf(c[n][1] - mn0); ts0 += c[n][1];
            c[n][2] = __expf(c[n][2] - mn1); ts1 += c[n][2];
            c[n][3] = __expf(c[n][3] - mn1); ts1 += c[n][3];
        }
        ts0 += __shfl_xor_sync(0xffffffffu, ts0, 1);
        ts0 += __shfl_xor_sync(0xffffffffu, ts0, 2);
        ts1 += __shfl_xor_sync(0xffffffffu, ts1, 1);
        ts1 += __shfl_xor_sync(0xffffffffu, ts1, 2);
        l0 = l0*al0 + ts0; l1 = l1*al1 + ts1;
        m0r = mn0; m1r = mn1;
        #pragma unroll
        for (int n = 0; n < 8; n++) {
            o[n][0] *= al0; o[n][1] *= al0;
            o[n][2] *= al1; o[n][3] *= al1;
        }

        uint32_t pa[4][4];
        #pragma unroll
        for (int kt = 0; kt < 4; kt++) {
            pa[kt][0] = pack_half2(c[2*kt][0],   c[2*kt][1]);
            pa[kt][1] = pack_half2(c[2*kt][2],   c[2*kt][3]);
            pa[kt][2] = pack_half2(c[2*kt+1][0], c[2*kt+1][1]);
            pa[kt][3] = pack_half2(c[2*kt+1][2], c[2*kt+1][3]);
        }

        #pragma unroll
        for (int kt = 0; kt < 4; kt++) {
            #pragma unroll
            for (int nh = 0; nh < 4; nh++) {
                uint32_t r0, r1, r2, r3;
                uint32_t addr = sV[buf] + (uint32_t)((kt*16 + (t & 15)) * LQ
                                                      + nh*16 + ((t >> 4) << 3)) * 2;
                LDSM_X4_T(r0, r1, r2, r3, addr);
                MMA_F16(o[2*nh][0], o[2*nh][1], o[2*nh][2], o[2*nh][3],
                        pa[kt][0], pa[kt][1], pa[kt][2], pa[kt][3], r0, r1);
                MMA_F16(o[2*nh+1][0], o[2*nh+1][1], o[2*nh+1][2], o[2*nh+1][3],
                        pa[kt][0], pa[kt][1], pa[kt][2], pa[kt][3], r2, r3);
            }
        }

        __syncthreads();
        buf = nb;
    }

    // normalize + write fp16 O into g_Of [B,S,D]
    float inv0 = (l0 > 0.f) ? (1.0f / l0) : 0.f;
    float inv1 = (l1 > 0.f) ? (1.0f / l1) : 0.f;
    int qr0 = q0 + w*16 + (t >> 2), qr1 = qr0 + 8;
    int dbase = (t & 3) * 2;
    #pragma unroll
    for (int n = 0; n < 8; n++) {
        int d = n*8 + dbase;
        size_t i0 = ((size_t)b*SS + qr0) * DD + h*DK + d;
        size_t i1 = ((size_t)b*SS + qr1) * DD + h*DK + d;
        __half2 h0 = __floats2half2_rn(o[n][0]*inv0, o[n][1]*inv0);
        __half2 h1 = __floats2half2_rn(o[n][2]*inv1, o[n][3]*inv1);
        *(__half2*)&g_Of[i0] = h0;
        *(__half2*)&g_Of[i1] = h1;
    }
}

// ---------------------------------------------------------------------------
extern "C" void kernel_launch(void* const* d_in, const int* in_sizes, int n_in,
                              void* d_out, int out_size)
{
    const float* q    = (const float*)d_in[0];
    const float* k    = (const float*)d_in[1];
    const float* v    = (const float*)d_in[2];
    const int*   mask = (const int*)  d_in[3];
    const float* Wq   = (const float*)d_in[4];
    const float* bq   = (const float*)d_in[5];
    const float* Wk   = (const float*)d_in[6];
    const float* bk   = (const float*)d_in[7];
    const float* Wv   = (const float*)d_in[8];
    const float* bv   = (const float*)d_in[9];
    const float* Wo   = (const float*)d_in[10];
    const float* bo   = (const float*)d_in[11];
    float* out = (float*)d_out;

    cudaFuncSetAttribute(mma_gemm_kernel,
                         cudaFuncAttributeMaxDynamicSharedMemorySize, GEMM_SMEM);

    // 1) fused fp32 -> fp16 conversions (one launch, 7 tensors)
    const int NIN4 = MROWS*DD/4;
    dim3 cgrid((NIN4 + 255) / 256, 7);
    conv_all_kernel<<<cgrid, 256>>>(q, k, v, Wq, Wk, Wv, Wo);

    // 2) fused QKV projections (fp16 mma.sync) -> fp16 split-head
    dim3 ggrid(DD/128, MROWS/128, 3);   // (8, 32, 3)
    mma_gemm_kernel<<<ggrid, 256, GEMM_SMEM>>>(bq, bk, bv, nullptr, 0);

    // 3) tensor-core flash attention (fp16), writes g_Of
    dim3 fgrid(SS/64, HH, BB);          // (32, 16, 2)
    flash_tc_kernel<<<fgrid, 128>>>(mask);

    // 4) output projection (fp16 mma.sync) -> fp32 out
    dim3 ogrid(DD/128, MROWS/128, 1);
    mma_gemm_kernel<<<ogrid, 256, GEMM_SMEM>>>(bo, nullptr, nullptr, out, 1);
}